// round 4
// baseline (speedup 1.0000x reference)
#include <cuda_runtime.h>
#include <math.h>

#define DM 1024      // d_model
#define DI 2048      // d_inner
#define DS 16        // d_state
#define DR 64        // dt_rank
#define BB 2         // batch
#define LL 1024      // seq len
#define MT 2048      // BB*LL (token count)
#define DBCW 96      // dt_rank + 2*d_state
#define KSPLIT 8     // split-K factor for x_proj

// ---- scratch (static device allocations; no runtime alloc) ----
__device__ float g_xz[(size_t)MT * 2 * DI];     // in_proj output [MT, 4096]
__device__ float g_xs[(size_t)MT * DI];         // conv+silu output (full precision)
__device__ float g_xsr[(size_t)MT * DI];        // conv+silu output (tf32-rounded, GEMM A)
__device__ float g_dbc[(size_t)MT * DBCW];      // x_proj output [MT, 96] (full)
__device__ float g_dtr[(size_t)MT * DR];        // delta_r rounded [MT, 64] (GEMM A)
__device__ float g_delta[(size_t)MT * DI];      // softplus(dt) [MT, 2048]
__device__ float g_y[(size_t)MT * DI];          // scan output, rounded (GEMM A)
__device__ float g_xr[(size_t)MT * DM];         // rounded input x
__device__ float g_w1r[(size_t)2 * DI * DM];    // rounded in_proj_w
__device__ float g_wxr[(size_t)DBCW * DI];      // rounded x_proj_w
__device__ float g_wdtr[(size_t)DI * DR];       // rounded dt_proj_w
__device__ float g_wor[(size_t)DM * DI];        // rounded out_proj_w
__device__ float g_xpart[(size_t)KSPLIT * MT * DBCW];  // split-K partials

__device__ __forceinline__ float softplusf(float x) {
    return (x > 20.f) ? x : log1pf(expf(x));
}

__device__ __forceinline__ unsigned f2tf(float f) {
    unsigned u;
    asm("cvt.rna.tf32.f32 %0, %1;" : "=r"(u) : "f"(f));
    return u;
}
__device__ __forceinline__ float roundtf(float f) { return __uint_as_float(f2tf(f)); }

__device__ __forceinline__ void mma_tf32(float c[4], const unsigned a[4], const unsigned b[2]) {
    asm("mma.sync.aligned.m16n8k8.row.col.f32.tf32.tf32.f32 "
        "{%0,%1,%2,%3}, {%4,%5,%6,%7}, {%8,%9}, {%0,%1,%2,%3};"
        : "+f"(c[0]), "+f"(c[1]), "+f"(c[2]), "+f"(c[3])
        : "r"(a[0]), "r"(a[1]), "r"(a[2]), "r"(a[3]), "r"(b[0]), "r"(b[1]));
}

__device__ __forceinline__ void cp16(float* smem, const float* g) {
    unsigned s = (unsigned)__cvta_generic_to_shared(smem);
    asm volatile("cp.async.cg.shared.global [%0], [%1], 16;" :: "r"(s), "l"(g));
}

// ============================================================================
// Prepass: tf32-round x and all GEMM weight operands (one launch, vec4).
// ============================================================================
#define N0V ((MT * DM) / 4)          // x
#define N1V ((2 * DI * DM) / 4)      // in_proj_w
#define N2V ((DBCW * DI) / 4)        // x_proj_w
#define N3V ((DI * DR) / 4)          // dt_proj_w
#define N4V ((DM * DI) / 4)          // out_proj_w
#define NTOTV (N0V + N1V + N2V + N3V + N4V)

__global__ __launch_bounds__(256) void round_all(
    const float4* __restrict__ p0, const float4* __restrict__ p1,
    const float4* __restrict__ p2, const float4* __restrict__ p3,
    const float4* __restrict__ p4)
{
    int v = blockIdx.x * 256 + threadIdx.x;
    if (v >= NTOTV) return;
    const float4* src; float4* dst;
    if (v < N0V)                  { src = p0 + v; dst = (float4*)g_xr   + v; }
    else if ((v -= N0V) < N1V)    { src = p1 + v; dst = (float4*)g_w1r  + v; }
    else if ((v -= N1V) < N2V)    { src = p2 + v; dst = (float4*)g_wxr  + v; }
    else if ((v -= N2V) < N3V)    { src = p3 + v; dst = (float4*)g_wdtr + v; }
    else { v -= N3V;                src = p4 + v; dst = (float4*)g_wor  + v; }
    float4 a = *src;
    a.x = roundtf(a.x); a.y = roundtf(a.y); a.z = roundtf(a.z); a.w = roundtf(a.w);
    *dst = a;
}

// ============================================================================
// tf32 tensor-core GEMM: C[M,N] = A[M,K] * B[N,K]^T (row-major, K contiguous)
// Operands MUST already be tf32-rounded (raw bits fed to mma).
// CTA tile 128 x WN, 128 threads (4 warps as 2x2), warp tile 64 x WN/2,
// mma.m16n8k8, BK=16, double-buffered cp.async, smem stride 20 (bank-free).
// EPI 1: C = softplus(C + bias[n]).  SPLIT: blockIdx.z selects K-chunk,
// writes partial to C + z*MT*ldc.
// ============================================================================
template<int WN, int EPI, int SPLIT>
__global__ __launch_bounds__(128) void gemm_mma(
    const float* __restrict__ A, int lda,
    const float* __restrict__ B, int ldb,
    float* __restrict__ C, int ldc,
    int K, const float* __restrict__ bias)
{
    constexpr int NI = WN / 16;   // n8 tiles per warp
    __shared__ __align__(16) float As[2][128 * 20];
    __shared__ __align__(16) float Bs[2][WN * 20];

    const int t    = threadIdx.x;
    const int wid  = t >> 5;
    const int lane = t & 31;
    const int gid  = lane >> 2;
    const int tig  = lane & 3;
    const int m0   = blockIdx.y * 128;
    const int n0   = blockIdx.x * WN;
    const int wm   = (wid >> 1) * 64;
    const int wn   = (wid & 1) * (WN / 2);
    const int lr   = t >> 2;      // 0..31
    const int lk   = (t & 3) * 4; // 0,4,8,12

    if (SPLIT) {
        int kz = blockIdx.z;
        A += (size_t)kz * K;
        B += (size_t)kz * K;
        C += (size_t)kz * MT * ldc;
    }

    float acc[4][NI][4];
    #pragma unroll
    for (int mi = 0; mi < 4; mi++)
        #pragma unroll
        for (int ni = 0; ni < NI; ni++)
            #pragma unroll
            for (int j = 0; j < 4; j++) acc[mi][ni][j] = 0.f;

    const int niter = K >> 4;

    auto issue = [&](int buf, int k0) {
        #pragma unroll
        for (int h = 0; h < 4; h++) {
            int r = lr + h * 32;
            cp16(&As[buf][r * 20 + lk], A + (size_t)(m0 + r) * lda + k0 + lk);
        }
        #pragma unroll
        for (int h = 0; h < WN / 32; h++) {
            int r = lr + h * 32;
            cp16(&Bs[buf][r * 20 + lk], B + (size_t)(n0 + r) * ldb + k0 + lk);
        }
        asm volatile("cp.async.commit_group;");
    };

    issue(0, 0);

    for (int it = 0; it < niter; ++it) {
        asm volatile("cp.async.wait_group 0;");
        __syncthreads();
        if (it + 1 < niter) issue((it + 1) & 1, (it + 1) << 4);

        const float* as = As[it & 1];
        const float* bs = Bs[it & 1];

        #pragma unroll
        for (int ks = 0; ks < 2; ks++) {
            const int kb = ks * 8;
            unsigned bfr[NI][2];
            #pragma unroll
            for (int ni = 0; ni < NI; ni++) {
                int cb = wn + ni * 8 + gid;
                bfr[ni][0] = __float_as_uint(bs[cb * 20 + kb + tig]);
                bfr[ni][1] = __float_as_uint(bs[cb * 20 + kb + tig + 4]);
            }
            #pragma unroll
            for (int mi = 0; mi < 4; mi++) {
                int rb = wm + mi * 16 + gid;
                unsigned af[4];
                af[0] = __float_as_uint(as[rb * 20 + kb + tig]);
                af[1] = __float_as_uint(as[(rb + 8) * 20 + kb + tig]);
                af[2] = __float_as_uint(as[rb * 20 + kb + tig + 4]);
                af[3] = __float_as_uint(as[(rb + 8) * 20 + kb + tig + 4]);
                #pragma unroll
                for (int ni = 0; ni < NI; ni++)
                    mma_tf32(acc[mi][ni], af, bfr[ni]);
            }
        }
    }

    #pragma unroll
    for (int mi = 0; mi < 4; mi++) {
        int r0 = m0 + wm + mi * 16 + gid;
        int r1 = r0 + 8;
        #pragma unroll
        for (int ni = 0; ni < NI; ni++) {
            int col = n0 + wn + ni * 8 + tig * 2;
            float v0 = acc[mi][ni][0], v1 = acc[mi][ni][1];
            float v2 = acc[mi][ni][2], v3 = acc[mi][ni][3];
            if (EPI == 1) {
                float b0 = bias[col], b1 = bias[col + 1];
                v0 = softplusf(v0 + b0); v1 = softplusf(v1 + b1);
                v2 = softplusf(v2 + b0); v3 = softplusf(v3 + b1);
            }
            *(float2*)(C + (size_t)r0 * ldc + col) = make_float2(v0, v1);
            *(float2*)(C + (size_t)r1 * ldc + col) = make_float2(v2, v3);
        }
    }
}

// ============================================================================
// Split-K reduce for x_proj: g_dbc = sum_z g_xpart[z]; rounded delta_r -> g_dtr
// ============================================================================
__global__ __launch_bounds__(256) void reduce_dbc()
{
    int idx = blockIdx.x * 256 + threadIdx.x;   // 0 .. MT*96-1
    if (idx >= MT * DBCW) return;
    float s = 0.f;
    #pragma unroll
    for (int z = 0; z < KSPLIT; z++)
        s += g_xpart[(size_t)z * MT * DBCW + idx];
    g_dbc[idx] = s;
    int m = idx / DBCW, c = idx - m * DBCW;
    if (c < DR) g_dtr[m * DR + c] = roundtf(s);
}

// ============================================================================
// Fused causal depthwise conv (k=4) + bias + SiLU.
// Writes g_xs (full, for scan) and g_xsr (tf32-rounded, x_proj A operand).
// ============================================================================
__global__ __launch_bounds__(256) void conv_silu(
    const float* __restrict__ w, const float* __restrict__ bias)
{
    int idx = blockIdx.x * 256 + threadIdx.x;   // 0 .. MT*DI-1
    int d = idx & (DI - 1);
    int m = idx >> 11;
    int l = m & (LL - 1);
    float acc = bias[d];
    const float* wd = w + d * 4;
    #pragma unroll
    for (int k = 0; k < 4; k++) {
        int lp = l - 3 + k;
        if (lp >= 0)
            acc = fmaf(g_xz[(size_t)(m - 3 + k) * (2 * DI) + d], wd[k], acc);
    }
    float sig = 1.f / (1.f + __expf(-acc));
    float v = acc * sig;
    g_xs[idx]  = v;
    g_xsr[idx] = roundtf(v);
}

// ============================================================================
// Selective scan. 16 lanes per (b,d) channel, one lane per state n.
// Epilogue (lane n==0): g_y = round_tf32((y + D*xs) * silu(z))  [out_proj A]
// ============================================================================
__global__ __launch_bounds__(256) void scan_kernel(
    const float* __restrict__ A_log, const float* __restrict__ Dp)
{
    int tid = blockIdx.x * 256 + threadIdx.x;
    int n  = tid & 15;
    int hw = tid >> 4;
    int b  = hw >> 11;
    int d  = hw & (DI - 1);

    float Ac = -__expf(A_log[d * DS + n]);
    float Dd = Dp[d];
    float h = 0.f;
    const int mbase = b * LL;
    const float* dbcB = g_dbc + DR + n;
    const float* dbcC = g_dbc + DR + DS + n;

    for (int l = 0; l < LL; l++) {
        int m = mbase + l;
        float dv = g_delta[(size_t)m * DI + d];
        float xv = g_xs[(size_t)m * DI + d];
        float Bv = dbcB[(size_t)m * DBCW];
        float Cv = dbcC[(size_t)m * DBCW];
        float dA = __expf(dv * Ac);
        h = fmaf(dA, h, dv * xv * Bv);
        float s = h * Cv;
        s += __shfl_xor_sync(0xffffffffu, s, 8);
        s += __shfl_xor_sync(0xffffffffu, s, 4);
        s += __shfl_xor_sync(0xffffffffu, s, 2);
        s += __shfl_xor_sync(0xffffffffu, s, 1);
        if (n == 0) {
            float zv = g_xz[(size_t)m * (2 * DI) + DI + d];
            float y = fmaf(Dd, xv, s);
            float sig = 1.f / (1.f + __expf(-zv));
            g_y[(size_t)m * DI + d] = roundtf(y * zv * sig);
        }
    }
}

// ============================================================================
// Launcher
// ============================================================================
extern "C" void kernel_launch(void* const* d_in, const int* in_sizes, int n_in,
                              void* d_out, int out_size)
{
    const float* x          = (const float*)d_in[0];
    const float* in_proj_w  = (const float*)d_in[1];
    const float* conv_w     = (const float*)d_in[2];
    const float* conv_b     = (const float*)d_in[3];
    const float* x_proj_w   = (const float*)d_in[4];
    const float* dt_proj_w  = (const float*)d_in[5];
    const float* dt_proj_b  = (const float*)d_in[6];
    const float* A_log      = (const float*)d_in[7];
    const float* Dvec       = (const float*)d_in[8];
    const float* out_proj_w = (const float*)d_in[9];
    float* out = (float*)d_out;

    float *xr, *w1r, *xsr, *wxr, *dtr, *wdtr, *delta, *y, *wor, *xz, *xpart;
    cudaGetSymbolAddress((void**)&xr,    g_xr);
    cudaGetSymbolAddress((void**)&w1r,   g_w1r);
    cudaGetSymbolAddress((void**)&xsr,   g_xsr);
    cudaGetSymbolAddress((void**)&wxr,   g_wxr);
    cudaGetSymbolAddress((void**)&dtr,   g_dtr);
    cudaGetSymbolAddress((void**)&wdtr,  g_wdtr);
    cudaGetSymbolAddress((void**)&delta, g_delta);
    cudaGetSymbolAddress((void**)&y,     g_y);
    cudaGetSymbolAddress((void**)&wor,   g_wor);
    cudaGetSymbolAddress((void**)&xz,    g_xz);
    cudaGetSymbolAddress((void**)&xpart, g_xpart);

    // 0) tf32-round x + all weights (one launch)
    round_all<<<(NTOTV + 255) / 256, 256>>>(
        (const float4*)x, (const float4*)in_proj_w, (const float4*)x_proj_w,
        (const float4*)dt_proj_w, (const float4*)out_proj_w);

    // 1) in_proj: [2048,1024] x [4096,1024]^T -> [2048,4096]
    gemm_mma<128, 0, 0><<<dim3((2 * DI) / 128, MT / 128), 128>>>(
        xr, DM, w1r, DM, xz, 2 * DI, DM, nullptr);

    // 2) causal depthwise conv + SiLU -> g_xs (full) + g_xsr (rounded)
    conv_silu<<<(MT * DI) / 256, 256>>>(conv_w, conv_b);

    // 3) x_proj split-K: [2048,2048] x [96,2048]^T -> 8 partials [2048,96]
    gemm_mma<96, 0, 1><<<dim3(1, MT / 128, KSPLIT), 128>>>(
        xsr, DI, wxr, DI, xpart, DBCW, DI / KSPLIT, nullptr);
    reduce_dbc<<<(MT * DBCW + 255) / 256, 256>>>();

    // 4) dt_proj + softplus: [2048,64] x [2048,64]^T -> [2048,2048]
    gemm_mma<128, 1, 0><<<dim3(DI / 128, MT / 128), 128>>>(
        dtr, DR, wdtr, DR, delta, DI, DR, dt_proj_b);

    // 5) selective scan + gating -> g_y (rounded)
    scan_kernel<<<(BB * DI * DS) / 256, 256>>>(A_log, Dvec);

    // 6) out_proj: [2048,2048] x [1024,2048]^T -> [2048,1024]
    gemm_mma<128, 0, 0><<<dim3(DM / 128, MT / 128), 128>>>(
        y, DI, wor, DI, out, DM, DI, nullptr);
}

// round 6
// speedup vs baseline: 1.3024x; 1.3024x over previous
#include <cuda_runtime.h>
#include <math.h>

#define DM 1024      // d_model
#define DI 2048      // d_inner
#define DS 16        // d_state
#define DR 64        // dt_rank
#define BB 2         // batch
#define LL 1024      // seq len
#define MT 2048      // BB*LL (token count)
#define DBCW 96      // dt_rank + 2*d_state
#define KSPLIT 8     // split-K factor for x_proj

// ---- scratch (static device allocations; no runtime alloc) ----
__device__ float g_xz[(size_t)MT * 2 * DI];     // in_proj output [MT, 4096]
__device__ float g_xs[(size_t)MT * DI];         // conv+silu output (full precision)
__device__ float g_xsr[(size_t)MT * DI];        // conv+silu output (tf32-rounded)
__device__ float g_dbc[(size_t)MT * DBCW];      // x_proj output [MT, 96] (full)
__device__ float g_dtr[(size_t)MT * DR];        // delta_r rounded [MT, 64]
__device__ float g_delta[(size_t)MT * DI];      // softplus(dt) [MT, 2048]
__device__ float g_y[(size_t)MT * DI];          // scan output, rounded
__device__ float g_xr[(size_t)MT * DM];         // rounded input x
__device__ float g_w1r[(size_t)2 * DI * DM];    // rounded in_proj_w
__device__ float g_wxr[(size_t)DBCW * DI];      // rounded x_proj_w
__device__ float g_wdtr[(size_t)DI * DR];       // rounded dt_proj_w
__device__ float g_wor[(size_t)DM * DI];        // rounded out_proj_w
__device__ float g_xpart[(size_t)KSPLIT * MT * DBCW];  // split-K partials

__device__ __forceinline__ float softplusf(float x) {
    return (x > 20.f) ? x : log1pf(expf(x));
}

__device__ __forceinline__ unsigned f2tf(float f) {
    unsigned u;
    asm("cvt.rna.tf32.f32 %0, %1;" : "=r"(u) : "f"(f));
    return u;
}
__device__ __forceinline__ float roundtf(float f) { return __uint_as_float(f2tf(f)); }

__device__ __forceinline__ void mma_tf32(float c[4], const unsigned a[4], const unsigned b[2]) {
    asm("mma.sync.aligned.m16n8k8.row.col.f32.tf32.tf32.f32 "
        "{%0,%1,%2,%3}, {%4,%5,%6,%7}, {%8,%9}, {%0,%1,%2,%3};"
        : "+f"(c[0]), "+f"(c[1]), "+f"(c[2]), "+f"(c[3])
        : "r"(a[0]), "r"(a[1]), "r"(a[2]), "r"(a[3]), "r"(b[0]), "r"(b[1]));
}

__device__ __forceinline__ void cp16(float* smem, const float* g) {
    unsigned s = (unsigned)__cvta_generic_to_shared(smem);
    asm volatile("cp.async.cg.shared.global [%0], [%1], 16;" :: "r"(s), "l"(g));
}

// ============================================================================
// Prepass: tf32-round x and all GEMM weight operands (one launch, vec4).
// ============================================================================
#define N0V ((MT * DM) / 4)          // x
#define N1V ((2 * DI * DM) / 4)      // in_proj_w
#define N2V ((DBCW * DI) / 4)        // x_proj_w
#define N3V ((DI * DR) / 4)          // dt_proj_w
#define N4V ((DM * DI) / 4)          // out_proj_w
#define NTOTV (N0V + N1V + N2V + N3V + N4V)

__global__ __launch_bounds__(256) void round_all(
    const float4* __restrict__ p0, const float4* __restrict__ p1,
    const float4* __restrict__ p2, const float4* __restrict__ p3,
    const float4* __restrict__ p4)
{
    int v = blockIdx.x * 256 + threadIdx.x;
    if (v >= NTOTV) return;
    const float4* src; float4* dst;
    if (v < N0V)                  { src = p0 + v; dst = (float4*)g_xr   + v; }
    else if ((v -= N0V) < N1V)    { src = p1 + v; dst = (float4*)g_w1r  + v; }
    else if ((v -= N1V) < N2V)    { src = p2 + v; dst = (float4*)g_wxr  + v; }
    else if ((v -= N2V) < N3V)    { src = p3 + v; dst = (float4*)g_wdtr + v; }
    else { v -= N3V;                src = p4 + v; dst = (float4*)g_wor  + v; }
    float4 a = *src;
    a.x = roundtf(a.x); a.y = roundtf(a.y); a.z = roundtf(a.z); a.w = roundtf(a.w);
    *dst = a;
}

// ============================================================================
// tf32 tensor-core GEMM: C[M,N] = A[M,K] * B[N,K]^T (row-major, K contiguous)
// Operands MUST already be tf32-rounded (raw bits fed to mma).
// CTA tile 128 x (NT*32), 256 threads (8 warps as 2x4), warp tile 64 x (NT*8).
// mma.m16n8k8, BK=16, double-buffered cp.async, smem stride 20 (bank-free).
// __launch_bounds__(256,2) -> <=128 regs -> 2 CTAs/SM -> 50% occupancy.
// EPI 1: C = softplus(C + bias[n]).  SPLIT: blockIdx.z = K-chunk, partial out.
// ============================================================================
template<int NT, int EPI, int SPLIT>
__global__ __launch_bounds__(256, 2) void gemm_mma(
    const float* __restrict__ A, int lda,
    const float* __restrict__ B, int ldb,
    float* __restrict__ C, int ldc,
    int K, const float* __restrict__ bias)
{
    constexpr int BN = NT * 32;
    __shared__ __align__(16) float As[2][128 * 20];
    __shared__ __align__(16) float Bs[2][BN * 20];

    const int t    = threadIdx.x;
    const int wid  = t >> 5;
    const int lane = t & 31;
    const int gid  = lane >> 2;
    const int tig  = lane & 3;
    const int m0   = blockIdx.y * 128;
    const int n0   = blockIdx.x * BN;
    const int wm   = (wid >> 2) * 64;        // 0 or 64
    const int wn   = (wid & 3) * (NT * 8);   // warp col offset
    const int lr   = t >> 2;      // 0..63
    const int lk   = (t & 3) * 4; // 0,4,8,12

    if (SPLIT) {
        int kz = blockIdx.z;
        A += (size_t)kz * K;
        B += (size_t)kz * K;
        C += (size_t)kz * MT * ldc;
    }

    float acc[4][NT][4];
    #pragma unroll
    for (int mi = 0; mi < 4; mi++)
        #pragma unroll
        for (int ni = 0; ni < NT; ni++)
            #pragma unroll
            for (int j = 0; j < 4; j++) acc[mi][ni][j] = 0.f;

    const int niter = K >> 4;

    auto issue = [&](int buf, int k0) {
        #pragma unroll
        for (int h = 0; h < 2; h++) {
            int r = lr + h * 64;
            cp16(&As[buf][r * 20 + lk], A + (size_t)(m0 + r) * lda + k0 + lk);
        }
        #pragma unroll
        for (int h = 0; h < (BN + 63) / 64; h++) {
            int r = lr + h * 64;
            if ((BN % 64 == 0) || (r < BN))
                cp16(&Bs[buf][r * 20 + lk], B + (size_t)(n0 + r) * ldb + k0 + lk);
        }
        asm volatile("cp.async.commit_group;");
    };

    issue(0, 0);

    for (int it = 0; it < niter; ++it) {
        asm volatile("cp.async.wait_group 0;");
        __syncthreads();
        if (it + 1 < niter) issue((it + 1) & 1, (it + 1) << 4);

        const float* as = As[it & 1];
        const float* bs = Bs[it & 1];

        #pragma unroll
        for (int ks = 0; ks < 2; ks++) {
            const int kb = ks * 8;
            unsigned bfr[NT][2];
            #pragma unroll
            for (int ni = 0; ni < NT; ni++) {
                int cb = wn + ni * 8 + gid;
                bfr[ni][0] = __float_as_uint(bs[cb * 20 + kb + tig]);
                bfr[ni][1] = __float_as_uint(bs[cb * 20 + kb + tig + 4]);
            }
            #pragma unroll
            for (int mi = 0; mi < 4; mi++) {
                int rb = wm + mi * 16 + gid;
                unsigned af[4];
                af[0] = __float_as_uint(as[rb * 20 + kb + tig]);
                af[1] = __float_as_uint(as[(rb + 8) * 20 + kb + tig]);
                af[2] = __float_as_uint(as[rb * 20 + kb + tig + 4]);
                af[3] = __float_as_uint(as[(rb + 8) * 20 + kb + tig + 4]);
                #pragma unroll
                for (int ni = 0; ni < NT; ni++)
                    mma_tf32(acc[mi][ni], af, bfr[ni]);
            }
        }
        __syncthreads();
    }

    #pragma unroll
    for (int mi = 0; mi < 4; mi++) {
        int r0 = m0 + wm + mi * 16 + gid;
        int r1 = r0 + 8;
        #pragma unroll
        for (int ni = 0; ni < NT; ni++) {
            int col = n0 + wn + ni * 8 + tig * 2;
            float v0 = acc[mi][ni][0], v1 = acc[mi][ni][1];
            float v2 = acc[mi][ni][2], v3 = acc[mi][ni][3];
            if (EPI == 1) {
                float b0 = bias[col], b1 = bias[col + 1];
                v0 = softplusf(v0 + b0); v1 = softplusf(v1 + b1);
                v2 = softplusf(v2 + b0); v3 = softplusf(v3 + b1);
            }
            *(float2*)(C + (size_t)r0 * ldc + col) = make_float2(v0, v1);
            *(float2*)(C + (size_t)r1 * ldc + col) = make_float2(v2, v3);
        }
    }
}

// ============================================================================
// Split-K reduce for x_proj: g_dbc = sum_z g_xpart[z]; rounded delta_r -> g_dtr
// ============================================================================
__global__ __launch_bounds__(256) void reduce_dbc()
{
    int idx = blockIdx.x * 256 + threadIdx.x;   // 0 .. MT*96-1
    if (idx >= MT * DBCW) return;
    float s = 0.f;
    #pragma unroll
    for (int z = 0; z < KSPLIT; z++)
        s += g_xpart[(size_t)z * MT * DBCW + idx];
    g_dbc[idx] = s;
    int m = idx / DBCW, c = idx - m * DBCW;
    if (c < DR) g_dtr[m * DR + c] = roundtf(s);
}

// ============================================================================
// Fused causal depthwise conv (k=4) + bias + SiLU.
// Writes g_xs (full, for scan) and g_xsr (tf32-rounded, x_proj A operand).
// ============================================================================
__global__ __launch_bounds__(256) void conv_silu(
    const float* __restrict__ w, const float* __restrict__ bias)
{
    int idx = blockIdx.x * 256 + threadIdx.x;   // 0 .. MT*DI-1
    int d = idx & (DI - 1);
    int m = idx >> 11;
    int l = m & (LL - 1);
    float acc = bias[d];
    const float* wd = w + d * 4;
    #pragma unroll
    for (int k = 0; k < 4; k++) {
        int lp = l - 3 + k;
        if (lp >= 0)
            acc = fmaf(g_xz[(size_t)(m - 3 + k) * (2 * DI) + d], wd[k], acc);
    }
    float sig = 1.f / (1.f + __expf(-acc));
    float v = acc * sig;
    g_xs[idx]  = v;
    g_xsr[idx] = roundtf(v);
}

// ============================================================================
// Selective scan. 16 lanes per (b,d) channel, one lane per state n.
// Software-pipelined: block-of-4 register prefetch hides L2 latency; the
// only loop-carried chain is h = exp(dv*Ac)*h + dv*xs*B (~40cy/step).
// Epilogue (lane n==0): g_y = round_tf32((y + D*xs) * silu(z))
// ============================================================================
__global__ __launch_bounds__(256) void scan_kernel(
    const float* __restrict__ A_log, const float* __restrict__ Dp)
{
    int tid = blockIdx.x * 256 + threadIdx.x;
    int n  = tid & 15;
    int hw = tid >> 4;
    int b  = hw >> 11;
    int d  = hw & (DI - 1);

    float Ac = -__expf(A_log[d * DS + n]);
    float Dd = Dp[d];
    float h = 0.f;
    const int mbase = b * LL;
    const float* pd   = g_delta + d;
    const float* px   = g_xs + d;
    const float* dbcB = g_dbc + DR + n;
    const float* dbcC = g_dbc + DR + DS + n;

    float cdv[4], cxv[4], cBv[4], cCv[4];
    float ndv[4], nxv[4], nBv[4], nCv[4];

    #pragma unroll
    for (int j = 0; j < 4; j++) {
        size_t m = mbase + j;
        cdv[j] = pd[m * DI];
        cxv[j] = px[m * DI];
        cBv[j] = dbcB[m * DBCW];
        cCv[j] = dbcC[m * DBCW];
    }

    for (int lb = 0; lb < LL; lb += 4) {
        if (lb + 4 < LL) {
            #pragma unroll
            for (int j = 0; j < 4; j++) {
                size_t m = mbase + lb + 4 + j;
                ndv[j] = pd[m * DI];
                nxv[j] = px[m * DI];
                nBv[j] = dbcB[m * DBCW];
                nCv[j] = dbcC[m * DBCW];
            }
        }
        #pragma unroll
        for (int j = 0; j < 4; j++) {
            int m = mbase + lb + j;
            float dv = cdv[j], xv = cxv[j];
            float dA = __expf(dv * Ac);
            h = fmaf(dA, h, dv * xv * cBv[j]);
            float s = h * cBv[j] * 0.f + h * cCv[j];   // s = h*C
            s += __shfl_xor_sync(0xffffffffu, s, 8);
            s += __shfl_xor_sync(0xffffffffu, s, 4);
            s += __shfl_xor_sync(0xffffffffu, s, 2);
            s += __shfl_xor_sync(0xffffffffu, s, 1);
            if (n == 0) {
                float zv = g_xz[(size_t)m * (2 * DI) + DI + d];
                float y = fmaf(Dd, xv, s);
                float sig = 1.f / (1.f + __expf(-zv));
                g_y[(size_t)m * DI + d] = roundtf(y * zv * sig);
            }
        }
        #pragma unroll
        for (int j = 0; j < 4; j++) {
            cdv[j] = ndv[j]; cxv[j] = nxv[j];
            cBv[j] = nBv[j]; cCv[j] = nCv[j];
        }
    }
}

// ============================================================================
// Launcher
// ============================================================================
extern "C" void kernel_launch(void* const* d_in, const int* in_sizes, int n_in,
                              void* d_out, int out_size)
{
    const float* x          = (const float*)d_in[0];
    const float* in_proj_w  = (const float*)d_in[1];
    const float* conv_w     = (const float*)d_in[2];
    const float* conv_b     = (const float*)d_in[3];
    const float* x_proj_w   = (const float*)d_in[4];
    const float* dt_proj_w  = (const float*)d_in[5];
    const float* dt_proj_b  = (const float*)d_in[6];
    const float* A_log      = (const float*)d_in[7];
    const float* Dvec       = (const float*)d_in[8];
    const float* out_proj_w = (const float*)d_in[9];
    float* out = (float*)d_out;

    float *xr, *w1r, *xsr, *wxr, *dtr, *wdtr, *delta, *y, *wor, *xz, *xpart;
    cudaGetSymbolAddress((void**)&xr,    g_xr);
    cudaGetSymbolAddress((void**)&w1r,   g_w1r);
    cudaGetSymbolAddress((void**)&xsr,   g_xsr);
    cudaGetSymbolAddress((void**)&wxr,   g_wxr);
    cudaGetSymbolAddress((void**)&dtr,   g_dtr);
    cudaGetSymbolAddress((void**)&wdtr,  g_wdtr);
    cudaGetSymbolAddress((void**)&delta, g_delta);
    cudaGetSymbolAddress((void**)&y,     g_y);
    cudaGetSymbolAddress((void**)&wor,   g_wor);
    cudaGetSymbolAddress((void**)&xz,    g_xz);
    cudaGetSymbolAddress((void**)&xpart, g_xpart);

    // 0) tf32-round x + all weights (one launch)
    round_all<<<(NTOTV + 255) / 256, 256>>>(
        (const float4*)x, (const float4*)in_proj_w, (const float4*)x_proj_w,
        (const float4*)dt_proj_w, (const float4*)out_proj_w);

    // 1) in_proj: [2048,1024] x [4096,1024]^T -> [2048,4096]
    gemm_mma<4, 0, 0><<<dim3((2 * DI) / 128, MT / 128), 256>>>(
        xr, DM, w1r, DM, xz, 2 * DI, DM, nullptr);

    // 2) causal depthwise conv + SiLU -> g_xs (full) + g_xsr (rounded)
    conv_silu<<<(MT * DI) / 256, 256>>>(conv_w, conv_b);

    // 3) x_proj split-K: [2048,2048] x [96,2048]^T -> 8 partials [2048,96]
    gemm_mma<3, 0, 1><<<dim3(1, MT / 128, KSPLIT), 256>>>(
        xsr, DI, wxr, DI, xpart, DBCW, DI / KSPLIT, nullptr);
    reduce_dbc<<<(MT * DBCW + 255) / 256, 256>>>();

    // 4) dt_proj + softplus: [2048,64] x [2048,64]^T -> [2048,2048]
    gemm_mma<4, 1, 0><<<dim3(DI / 128, MT / 128), 256>>>(
        dtr, DR, wdtr, DR, delta, DI, DR, dt_proj_b);

    // 5) selective scan + gating -> g_y (rounded)
    scan_kernel<<<(BB * DI * DS) / 256, 256>>>(A_log, Dvec);

    // 6) out_proj: [2048,2048] x [1024,2048]^T -> [2048,1024]
    gemm_mma<4, 0, 0><<<dim3(DM / 128, MT / 128), 256>>>(
        y, DI, wor, DI, out, DM, DI, nullptr);
}

// round 9
// speedup vs baseline: 1.3641x; 1.0474x over previous
#include <cuda_runtime.h>
#include <math.h>

#define DM 1024      // d_model
#define DI 2048      // d_inner
#define DS 16        // d_state
#define DR 64        // dt_rank
#define BB 2         // batch
#define LL 1024      // seq len
#define MT 2048      // BB*LL (token count)
#define DBCW 96      // dt_rank + 2*d_state
#define KSPLIT 16    // split-K factor for x_proj

// ---- scratch (static device allocations; no runtime alloc) ----
// All GEMM operand tensors (suffix r) are stored k16-PERMUTED: within each
// 16-col block, col c sits at (c&3)*4 + (c>>2). GEMM outputs (C) are normal.
__device__ float g_xz[(size_t)MT * 2 * DI];     // in_proj output [MT, 4096]
__device__ float g_xs[(size_t)MT * DI];         // conv+silu output (full, normal)
__device__ float g_xsr[(size_t)MT * DI];        // conv+silu (rounded, permuted)
__device__ float g_dbc[(size_t)MT * DBCW];      // x_proj output [MT, 96] (normal)
__device__ float g_dtr[(size_t)MT * DR];        // delta_r (rounded, permuted)
__device__ float g_delta[(size_t)MT * DI];      // softplus(dt) (normal)
__device__ float g_y[(size_t)MT * DI];          // scan out (rounded, permuted)
__device__ float g_xr[(size_t)MT * DM];         // x (rounded, permuted)
__device__ float g_w1r[(size_t)2 * DI * DM];    // in_proj_w (rounded, permuted)
__device__ float g_wxr[(size_t)DBCW * DI];      // x_proj_w (rounded, permuted)
__device__ float g_wdtr[(size_t)DI * DR];       // dt_proj_w (rounded, permuted)
__device__ float g_wor[(size_t)DM * DI];        // out_proj_w (rounded, permuted)
__device__ float g_xpart[(size_t)KSPLIT * MT * DBCW];  // split-K partials

__device__ __forceinline__ float softplusf(float x) {
    return (x > 20.f) ? x : log1pf(expf(x));
}

__device__ __forceinline__ unsigned f2tf(float f) {
    unsigned u;
    asm("cvt.rna.tf32.f32 %0, %1;" : "=r"(u) : "f"(f));
    return u;
}
__device__ __forceinline__ float roundtf(float f) { return __uint_as_float(f2tf(f)); }

// permuted column index within k16 blocks
__device__ __forceinline__ int permc(int c) {
    return (c & ~15) | ((c & 3) << 2) | ((c >> 2) & 3);
}

__device__ __forceinline__ void mma_tf32(float c[4], const unsigned a[4], const unsigned b[2]) {
    asm("mma.sync.aligned.m16n8k8.row.col.f32.tf32.tf32.f32 "
        "{%0,%1,%2,%3}, {%4,%5,%6,%7}, {%8,%9}, {%0,%1,%2,%3};"
        : "+f"(c[0]), "+f"(c[1]), "+f"(c[2]), "+f"(c[3])
        : "r"(a[0]), "r"(a[1]), "r"(a[2]), "r"(a[3]), "r"(b[0]), "r"(b[1]));
}

__device__ __forceinline__ void cp16(float* smem, const float* g) {
    unsigned s = (unsigned)__cvta_generic_to_shared(smem);
    asm volatile("cp.async.cg.shared.global [%0], [%1], 16;" :: "r"(s), "l"(g));
}

// ============================================================================
// Prepass: tf32-round AND k16-permute x + all GEMM weights.
// One thread = one 16-float block = a 4x4 transpose of float4s.
// ============================================================================
#define S0B ((MT * DM) / 16)
#define S1B ((2 * DI * DM) / 16)
#define S2B ((DBCW * DI) / 16)
#define S3B ((DI * DR) / 16)
#define S4B ((DM * DI) / 16)
#define NBLK (S0B + S1B + S2B + S3B + S4B)

__global__ __launch_bounds__(256) void round_perm(
    const float4* __restrict__ p0, const float4* __restrict__ p1,
    const float4* __restrict__ p2, const float4* __restrict__ p3,
    const float4* __restrict__ p4)
{
    int v = blockIdx.x * 256 + threadIdx.x;
    if (v >= NBLK) return;
    const float4* src; float4* dst;
    if (v < S0B)                { src = p0 + v * 4; dst = (float4*)g_xr   + v * 4; }
    else if ((v -= S0B) < S1B)  { src = p1 + v * 4; dst = (float4*)g_w1r  + v * 4; }
    else if ((v -= S1B) < S2B)  { src = p2 + v * 4; dst = (float4*)g_wxr  + v * 4; }
    else if ((v -= S2B) < S3B)  { src = p3 + v * 4; dst = (float4*)g_wdtr + v * 4; }
    else { v -= S3B;              src = p4 + v * 4; dst = (float4*)g_wor  + v * 4; }
    float4 s0 = src[0], s1 = src[1], s2 = src[2], s3 = src[3];
    dst[0] = make_float4(roundtf(s0.x), roundtf(s1.x), roundtf(s2.x), roundtf(s3.x));
    dst[1] = make_float4(roundtf(s0.y), roundtf(s1.y), roundtf(s2.y), roundtf(s3.y));
    dst[2] = make_float4(roundtf(s0.z), roundtf(s1.z), roundtf(s2.z), roundtf(s3.z));
    dst[3] = make_float4(roundtf(s0.w), roundtf(s1.w), roundtf(s2.w), roundtf(s3.w));
}

// ============================================================================
// tf32 tensor-core GEMM on k16-PERMUTED operands (pre-rounded to tf32 bits).
// C[M,N] = A[M,K]*B[N,K]^T. CTA 128 x (NT*32), 256 thr (8 warps 2x4),
// warp 64 x (NT*8), mma.m16n8k8, BK=16, double-buffered cp.async.
// Smem stride 16 floats: conflict-free LDS.128 fragment loads
// (A: 2 per mi per k16, B: 1 per ni per k16).
// EPI 1: C = softplus(C + bias[n]).  SPLIT: blockIdx.z = K-chunk partial.
// ============================================================================
template<int NT, int EPI, int SPLIT>
__global__ __launch_bounds__(256, 2) void gemm_mma(
    const float* __restrict__ A, int lda,
    const float* __restrict__ B, int ldb,
    float* __restrict__ C, int ldc,
    int K, const float* __restrict__ bias)
{
    constexpr int BN = NT * 32;
    __shared__ __align__(16) float As[2][128 * 16];
    __shared__ __align__(16) float Bs[2][BN * 16];

    const int t    = threadIdx.x;
    const int wid  = t >> 5;
    const int lane = t & 31;
    const int gid  = lane >> 2;
    const int tig  = lane & 3;
    const int m0   = blockIdx.y * 128;
    const int n0   = blockIdx.x * BN;
    const int wm   = (wid >> 2) * 64;        // 0 or 64
    const int wn   = (wid & 3) * (NT * 8);   // warp col offset
    const int lr   = t >> 2;      // 0..63
    const int lk   = (t & 3) * 4; // 0,4,8,12

    if (SPLIT) {
        int kz = blockIdx.z;
        A += (size_t)kz * K;
        B += (size_t)kz * K;
        C += (size_t)kz * MT * ldc;
    }

    float acc[4][NT][4];
    #pragma unroll
    for (int mi = 0; mi < 4; mi++)
        #pragma unroll
        for (int ni = 0; ni < NT; ni++)
            #pragma unroll
            for (int j = 0; j < 4; j++) acc[mi][ni][j] = 0.f;

    const int niter = K >> 4;

    auto issue = [&](int buf, int k0) {
        #pragma unroll
        for (int h = 0; h < 2; h++) {
            int r = lr + h * 64;
            cp16(&As[buf][r * 16 + lk], A + (size_t)(m0 + r) * lda + k0 + lk);
        }
        #pragma unroll
        for (int h = 0; h < (BN + 63) / 64; h++) {
            int r = lr + h * 64;
            if ((BN % 64 == 0) || (r < BN))
                cp16(&Bs[buf][r * 16 + lk], B + (size_t)(n0 + r) * ldb + k0 + lk);
        }
        asm volatile("cp.async.commit_group;");
    };

    issue(0, 0);

    for (int it = 0; it < niter; ++it) {
        asm volatile("cp.async.wait_group 0;");
        __syncthreads();
        if (it + 1 < niter) issue((it + 1) & 1, (it + 1) << 4);

        const float* as = As[it & 1];
        const float* bs = Bs[it & 1];

        // B fragments for the whole k16 tile: one LDS.128 per ni
        float4 bq[NT];
        #pragma unroll
        for (int ni = 0; ni < NT; ni++)
            bq[ni] = *(const float4*)&bs[(wn + ni * 8 + gid) * 16 + tig * 4];

        #pragma unroll
        for (int mi = 0; mi < 4; mi++) {
            int rb = wm + mi * 16 + gid;
            float4 a0 = *(const float4*)&as[rb * 16 + tig * 4];
            float4 a1 = *(const float4*)&as[(rb + 8) * 16 + tig * 4];
            {   // k8 step 0: original cols {tig, tig+4}
                unsigned af[4] = { __float_as_uint(a0.x), __float_as_uint(a1.x),
                                   __float_as_uint(a0.y), __float_as_uint(a1.y) };
                #pragma unroll
                for (int ni = 0; ni < NT; ni++) {
                    unsigned bf[2] = { __float_as_uint(bq[ni].x), __float_as_uint(bq[ni].y) };
                    mma_tf32(acc[mi][ni], af, bf);
                }
            }
            {   // k8 step 1: original cols {tig+8, tig+12}
                unsigned af[4] = { __float_as_uint(a0.z), __float_as_uint(a1.z),
                                   __float_as_uint(a0.w), __float_as_uint(a1.w) };
                #pragma unroll
                for (int ni = 0; ni < NT; ni++) {
                    unsigned bf[2] = { __float_as_uint(bq[ni].z), __float_as_uint(bq[ni].w) };
                    mma_tf32(acc[mi][ni], af, bf);
                }
            }
        }
    }

    #pragma unroll
    for (int mi = 0; mi < 4; mi++) {
        int r0 = m0 + wm + mi * 16 + gid;
        int r1 = r0 + 8;
        #pragma unroll
        for (int ni = 0; ni < NT; ni++) {
            int col = n0 + wn + ni * 8 + tig * 2;
            float v0 = acc[mi][ni][0], v1 = acc[mi][ni][1];
            float v2 = acc[mi][ni][2], v3 = acc[mi][ni][3];
            if (EPI == 1) {
                float b0 = bias[col], b1 = bias[col + 1];
                v0 = softplusf(v0 + b0); v1 = softplusf(v1 + b1);
                v2 = softplusf(v2 + b0); v3 = softplusf(v3 + b1);
            }
            *(float2*)(C + (size_t)r0 * ldc + col) = make_float2(v0, v1);
            *(float2*)(C + (size_t)r1 * ldc + col) = make_float2(v2, v3);
        }
    }
}

// ============================================================================
// Split-K reduce for x_proj: g_dbc = sum_z partials; delta_r -> g_dtr
// (rounded + permuted, the dt_proj A operand).
// ============================================================================
__global__ __launch_bounds__(256) void reduce_dbc()
{
    int idx = blockIdx.x * 256 + threadIdx.x;   // 0 .. MT*96-1
    if (idx >= MT * DBCW) return;
    float s = 0.f;
    #pragma unroll
    for (int z = 0; z < KSPLIT; z++)
        s += g_xpart[(size_t)z * MT * DBCW + idx];
    g_dbc[idx] = s;
    int m = idx / DBCW, c = idx - m * DBCW;
    if (c < DR) g_dtr[m * DR + permc(c)] = roundtf(s);
}

// ============================================================================
// Fused causal depthwise conv (k=4) + bias + SiLU.
// g_xs: full precision (scan). g_xsr: rounded + permuted (x_proj A operand).
// ============================================================================
__global__ __launch_bounds__(256) void conv_silu(
    const float* __restrict__ w, const float* __restrict__ bias)
{
    int idx = blockIdx.x * 256 + threadIdx.x;   // 0 .. MT*DI-1
    int d = idx & (DI - 1);
    int m = idx >> 11;
    int l = m & (LL - 1);
    float acc = bias[d];
    const float* wd = w + d * 4;
    #pragma unroll
    for (int k = 0; k < 4; k++) {
        int lp = l - 3 + k;
        if (lp >= 0)
            acc = fmaf(g_xz[(size_t)(m - 3 + k) * (2 * DI) + d], wd[k], acc);
    }
    float sig = 1.f / (1.f + __expf(-acc));
    float v = acc * sig;
    g_xs[idx] = v;
    g_xsr[(size_t)m * DI + permc(d)] = roundtf(v);
}

// ============================================================================
// Selective scan. 16 lanes per (b,d) channel, one lane per state n.
// Block-of-4 register prefetch; loop-carried chain = exp -> fma only.
// Epilogue (n==0): g_y[m, permc(d)] = round_tf32((y + D*xs) * silu(z))
// ============================================================================
__global__ __launch_bounds__(256) void scan_kernel(
    const float* __restrict__ A_log, const float* __restrict__ Dp)
{
    int tid = blockIdx.x * 256 + threadIdx.x;
    int n  = tid & 15;
    int hw = tid >> 4;
    int b  = hw >> 11;
    int d  = hw & (DI - 1);
    int pdi = permc(d);

    float Ac = -__expf(A_log[d * DS + n]);
    float Dd = Dp[d];
    float h = 0.f;
    const int mbase = b * LL;
    const float* pd   = g_delta + d;
    const float* px   = g_xs + d;
    const float* dbcB = g_dbc + DR + n;
    const float* dbcC = g_dbc + DR + DS + n;

    float cdv[4], cxv[4], cBv[4], cCv[4];
    float ndv[4], nxv[4], nBv[4], nCv[4];

    #pragma unroll
    for (int j = 0; j < 4; j++) {
        size_t m = mbase + j;
        cdv[j] = pd[m * DI];
        cxv[j] = px[m * DI];
        cBv[j] = dbcB[m * DBCW];
        cCv[j] = dbcC[m * DBCW];
    }

    for (int lb = 0; lb < LL; lb += 4) {
        if (lb + 4 < LL) {
            #pragma unroll
            for (int j = 0; j < 4; j++) {
                size_t m = mbase + lb + 4 + j;
                ndv[j] = pd[m * DI];
                nxv[j] = px[m * DI];
                nBv[j] = dbcB[m * DBCW];
                nCv[j] = dbcC[m * DBCW];
            }
        }
        #pragma unroll
        for (int j = 0; j < 4; j++) {
            int m = mbase + lb + j;
            float dv = cdv[j], xv = cxv[j];
            float dA = __expf(dv * Ac);
            h = fmaf(dA, h, dv * xv * cBv[j]);
            float s = h * cCv[j];
            s += __shfl_xor_sync(0xffffffffu, s, 8);
            s += __shfl_xor_sync(0xffffffffu, s, 4);
            s += __shfl_xor_sync(0xffffffffu, s, 2);
            s += __shfl_xor_sync(0xffffffffu, s, 1);
            if (n == 0) {
                float zv = g_xz[(size_t)m * (2 * DI) + DI + d];
                float y = fmaf(Dd, xv, s);
                float sig = 1.f / (1.f + __expf(-zv));
                g_y[(size_t)m * DI + pdi] = roundtf(y * zv * sig);
            }
        }
        #pragma unroll
        for (int j = 0; j < 4; j++) {
            cdv[j] = ndv[j]; cxv[j] = nxv[j];
            cBv[j] = nBv[j]; cCv[j] = nCv[j];
        }
    }
}

// ============================================================================
// Launcher
// ============================================================================
extern "C" void kernel_launch(void* const* d_in, const int* in_sizes, int n_in,
                              void* d_out, int out_size)
{
    const float* x          = (const float*)d_in[0];
    const float* in_proj_w  = (const float*)d_in[1];
    const float* conv_w     = (const float*)d_in[2];
    const float* conv_b     = (const float*)d_in[3];
    const float* x_proj_w   = (const float*)d_in[4];
    const float* dt_proj_w  = (const float*)d_in[5];
    const float* dt_proj_b  = (const float*)d_in[6];
    const float* A_log      = (const float*)d_in[7];
    const float* Dvec       = (const float*)d_in[8];
    const float* out_proj_w = (const float*)d_in[9];
    float* out = (float*)d_out;

    float *xr, *w1r, *xsr, *wxr, *dtr, *wdtr, *delta, *y, *wor, *xz, *xpart;
    cudaGetSymbolAddress((void**)&xr,    g_xr);
    cudaGetSymbolAddress((void**)&w1r,   g_w1r);
    cudaGetSymbolAddress((void**)&xsr,   g_xsr);
    cudaGetSymbolAddress((void**)&wxr,   g_wxr);
    cudaGetSymbolAddress((void**)&dtr,   g_dtr);
    cudaGetSymbolAddress((void**)&wdtr,  g_wdtr);
    cudaGetSymbolAddress((void**)&delta, g_delta);
    cudaGetSymbolAddress((void**)&y,     g_y);
    cudaGetSymbolAddress((void**)&wor,   g_wor);
    cudaGetSymbolAddress((void**)&xz,    g_xz);
    cudaGetSymbolAddress((void**)&xpart, g_xpart);

    // 0) tf32-round + permute x and all weights
    round_perm<<<(NBLK + 255) / 256, 256>>>(
        (const float4*)x, (const float4*)in_proj_w, (const float4*)x_proj_w,
        (const float4*)dt_proj_w, (const float4*)out_proj_w);

    // 1) in_proj: [2048,1024] x [4096,1024]^T -> [2048,4096]
    gemm_mma<4, 0, 0><<<dim3((2 * DI) / 128, MT / 128), 256>>>(
        xr, DM, w1r, DM, xz, 2 * DI, DM, nullptr);

    // 2) causal depthwise conv + SiLU
    conv_silu<<<(MT * DI) / 256, 256>>>(conv_w, conv_b);

    // 3) x_proj split-K: [2048,2048] x [96,2048]^T -> 16 partials [2048,96]
    gemm_mma<3, 0, 1><<<dim3(1, MT / 128, KSPLIT), 256>>>(
        xsr, DI, wxr, DI, xpart, DBCW, DI / KSPLIT, nullptr);
    reduce_dbc<<<(MT * DBCW + 255) / 256, 256>>>();

    // 4) dt_proj + softplus: [2048,64] x [2048,64]^T -> [2048,2048]
    gemm_mma<4, 1, 0><<<dim3(DI / 128, MT / 128), 256>>>(
        dtr, DR, wdtr, DR, delta, DI, DR, dt_proj_b);

    // 5) selective scan + gating -> g_y (rounded, permuted)
    scan_kernel<<<(BB * DI * DS) / 256, 256>>>(A_log, Dvec);

    // 6) out_proj: [2048,2048] x [1024,2048]^T -> [2048,1024]
    gemm_mma<4, 0, 0><<<dim3(DM / 128, MT / 128), 256>>>(
        y, DI, wor, DI, out, DM, DI, nullptr);
}

// round 13
// speedup vs baseline: 1.5310x; 1.1223x over previous
#include <cuda_runtime.h>
#include <cuda_fp16.h>
#include <math.h>
#include <stdint.h>

#define DM 1024      // d_model
#define DI 2048      // d_inner
#define DS 16        // d_state
#define DR 64        // dt_rank
#define BB 2         // batch
#define LL 1024      // seq len
#define MT 2048      // BB*LL (token count)
#define DBCW 96      // dt_rank + 2*d_state
#define KSPLIT 16    // split-K factor for x_proj

// ---- scratch (static device allocations; no runtime alloc) ----
// All fp16 GEMM operands are k32-PERMUTED: within each 32-col block, col c
// sits at p32(c) = ((c>>1)&3)*8 + ((c>>3)&3)*2 + (c&1), so a thread's
// m16n8k16 fragment (8 fp16) is one contiguous LDS.128.
__device__ float  g_xz[(size_t)MT * 2 * DI];    // in_proj output [MT, 4096]
__device__ float  g_xs[(size_t)MT * DI];        // conv+silu (full fp32)
__device__ float  g_dbc[(size_t)MT * DBCW];     // x_proj output (normal)
__device__ float  g_delta[(size_t)MT * DI];     // softplus(dt) (normal)
__device__ float  g_xpart[(size_t)KSPLIT * MT * DBCW];  // split-K partials
__device__ __half g_xh[(size_t)MT * DM];        // x (fp16, permuted)
__device__ __half g_w1h[(size_t)2 * DI * DM];   // in_proj_w
__device__ __half g_wxh[(size_t)DBCW * DI];     // x_proj_w
__device__ __half g_wdth[(size_t)DI * DR];      // dt_proj_w
__device__ __half g_woh[(size_t)DM * DI];       // out_proj_w
__device__ __half g_xsh[(size_t)MT * DI];       // conv+silu (fp16, permuted)
__device__ __half g_dth[(size_t)MT * DR];       // delta_r (fp16, permuted)
__device__ __half g_yh[(size_t)MT * DI];        // scan out (fp16, permuted)

__device__ __forceinline__ float softplusf(float x) {
    return (x > 20.f) ? x : log1pf(expf(x));
}
__host__ __device__ __forceinline__ int p32(int c) {
    return ((c >> 1) & 3) * 8 + ((c >> 4) & 1) * 4 + ((c >> 3) & 1) * 2 + (c & 1);
}
__device__ __forceinline__ int permidx(int c) {   // permute within 32-blocks
    return (c & ~31) | p32(c & 31);
}
__device__ __forceinline__ void mma_f16(float c[4],
    uint32_t a0, uint32_t a1, uint32_t a2, uint32_t a3, uint32_t b0, uint32_t b1) {
    asm("mma.sync.aligned.m16n8k16.row.col.f32.f16.f16.f32 "
        "{%0,%1,%2,%3}, {%4,%5,%6,%7}, {%8,%9}, {%0,%1,%2,%3};"
        : "+f"(c[0]), "+f"(c[1]), "+f"(c[2]), "+f"(c[3])
        : "r"(a0), "r"(a1), "r"(a2), "r"(a3), "r"(b0), "r"(b1));
}
__device__ __forceinline__ void cp16h(const __half* smem, const __half* g) {
    unsigned s = (unsigned)__cvta_generic_to_shared(smem);
    asm volatile("cp.async.cg.shared.global [%0], [%1], 16;" :: "r"(s), "l"(g));
}

// ============================================================================
// Prepass: fp16-convert + k32-permute x and all GEMM weights.
// One thread = one 32-float block (128B in, 64B out).
// ============================================================================
#define B0 (MT * DM / 32)
#define B1 (2 * DI * DM / 32)
#define B2 (DBCW * DI / 32)
#define B3 (DI * DR / 32)
#define B4 (DM * DI / 32)
#define NBLKH (B0 + B1 + B2 + B3 + B4)

__global__ __launch_bounds__(256) void to_half_perm(
    const float* __restrict__ p0, const float* __restrict__ p1,
    const float* __restrict__ p2, const float* __restrict__ p3,
    const float* __restrict__ p4)
{
    int v = blockIdx.x * 256 + threadIdx.x;
    if (v >= NBLKH) return;
    const float* s; __half* d;
    if (v < B0)               { s = p0; d = g_xh;   }
    else if ((v -= B0) < B1)  { s = p1; d = g_w1h;  }
    else if ((v -= B1) < B2)  { s = p2; d = g_wxh;  }
    else if ((v -= B2) < B3)  { s = p3; d = g_wdth; }
    else { v -= B3;             s = p4; d = g_woh;  }
    size_t off = (size_t)v * 32;
    union { __half h[32]; uint4 u[4]; } out;
    #pragma unroll
    for (int q = 0; q < 8; q++) {
        float4 a = *(const float4*)(s + off + q * 4);
        out.h[p32(q * 4 + 0)] = __float2half_rn(a.x);
        out.h[p32(q * 4 + 1)] = __float2half_rn(a.y);
        out.h[p32(q * 4 + 2)] = __float2half_rn(a.z);
        out.h[p32(q * 4 + 3)] = __float2half_rn(a.w);
    }
    uint4* d4 = (uint4*)(d + off);
    d4[0] = out.u[0]; d4[1] = out.u[1]; d4[2] = out.u[2]; d4[3] = out.u[3];
}

// ============================================================================
// fp16 tensor-core GEMM on k32-permuted operands, fp32 accumulate.
// C[M,N] = A[M,K]*B[N,K]^T. CTA 128 x (NT*32), 256 thr (8 warps 2x4),
// warp 64 x (NT*8), mma.m16n8k16, BK=32, double-buffered cp.async.
// Per k32 per warp: A 8 LDS.128, B NT LDS.128, 8*NT mma.
// EPI 1: C = softplus(C + bias[n]).  SPLIT: blockIdx.z = K-chunk partial.
// ============================================================================
template<int NT, int EPI, int SPLIT>
__global__ __launch_bounds__(256, 2) void gemm_h(
    const __half* __restrict__ A, int lda,
    const __half* __restrict__ B, int ldb,
    float* __restrict__ C, int ldc,
    int K, const float* __restrict__ bias)
{
    constexpr int BN = NT * 32;
    __shared__ __align__(16) __half As[2][128 * 32];
    __shared__ __align__(16) __half Bs[2][BN * 32];

    const int t    = threadIdx.x;
    const int wid  = t >> 5;
    const int lane = t & 31;
    const int gid  = lane >> 2;
    const int tig  = lane & 3;
    const int m0   = blockIdx.y * 128;
    const int n0   = blockIdx.x * BN;
    const int wm   = (wid >> 2) * 64;
    const int wn   = (wid & 3) * (NT * 8);

    const __half* Ab = A; const __half* Bb = B; float* Cb = C;
    if (SPLIT) {
        int kz = blockIdx.z;
        Ab += (size_t)kz * K;
        Bb += (size_t)kz * K;
        Cb += (size_t)kz * MT * ldc;
    }

    float acc[4][NT][4];
    #pragma unroll
    for (int mi = 0; mi < 4; mi++)
        #pragma unroll
        for (int ni = 0; ni < NT; ni++)
            #pragma unroll
            for (int j = 0; j < 4; j++) acc[mi][ni][j] = 0.f;

    const int niter = K >> 5;

    // granule layout: g -> row = g>>2, 16B chunk = (g&3)*8 halfs
    auto issue = [&](int buf, int k0) {
        #pragma unroll
        for (int i = 0; i < 2; i++) {               // A: 512 granules
            int g = t + 256 * i;
            int r = g >> 2, c8 = (g & 3) * 8;
            cp16h(&As[buf][r * 32 + c8], Ab + (size_t)(m0 + r) * lda + k0 + c8);
        }
        #pragma unroll
        for (int i = 0; i < (BN * 4 + 255) / 256; i++) {  // B: BN*4 granules
            int g = t + 256 * i;
            if ((BN * 4) % 256 == 0 || g < BN * 4) {
                int r = g >> 2, c8 = (g & 3) * 8;
                cp16h(&Bs[buf][r * 32 + c8], Bb + (size_t)(n0 + r) * ldb + k0 + c8);
            }
        }
        asm volatile("cp.async.commit_group;");
    };

    issue(0, 0);

    for (int it = 0; it < niter; ++it) {
        asm volatile("cp.async.wait_group 0;");
        __syncthreads();
        if (it + 1 < niter) issue((it + 1) & 1, (it + 1) << 5);

        const __half* as = As[it & 1];
        const __half* bs = Bs[it & 1];

        uint4 bq[NT];
        #pragma unroll
        for (int ni = 0; ni < NT; ni++)
            bq[ni] = *(const uint4*)&bs[(wn + ni * 8 + gid) * 32 + tig * 8];

        #pragma unroll
        for (int mi = 0; mi < 4; mi++) {
            int r = wm + mi * 16 + gid;
            uint4 a0 = *(const uint4*)&as[r * 32 + tig * 8];
            uint4 a1 = *(const uint4*)&as[(r + 8) * 32 + tig * 8];
            #pragma unroll
            for (int ni = 0; ni < NT; ni++) {
                mma_f16(acc[mi][ni], a0.x, a1.x, a0.y, a1.y, bq[ni].x, bq[ni].y);
                mma_f16(acc[mi][ni], a0.z, a1.z, a0.w, a1.w, bq[ni].z, bq[ni].w);
            }
        }
    }

    #pragma unroll
    for (int mi = 0; mi < 4; mi++) {
        int r0 = m0 + wm + mi * 16 + gid;
        int r1 = r0 + 8;
        #pragma unroll
        for (int ni = 0; ni < NT; ni++) {
            int col = n0 + wn + ni * 8 + tig * 2;
            float v0 = acc[mi][ni][0], v1 = acc[mi][ni][1];
            float v2 = acc[mi][ni][2], v3 = acc[mi][ni][3];
            if (EPI == 1) {
                float b0 = bias[col], b1 = bias[col + 1];
                v0 = softplusf(v0 + b0); v1 = softplusf(v1 + b1);
                v2 = softplusf(v2 + b0); v3 = softplusf(v3 + b1);
            }
            *(float2*)(Cb + (size_t)r0 * ldc + col) = make_float2(v0, v1);
            *(float2*)(Cb + (size_t)r1 * ldc + col) = make_float2(v2, v3);
        }
    }
}

// ============================================================================
// Split-K reduce for x_proj; delta_r -> g_dth (fp16, permuted)
// ============================================================================
__global__ __launch_bounds__(256) void reduce_dbc()
{
    int idx = blockIdx.x * 256 + threadIdx.x;
    if (idx >= MT * DBCW) return;
    float s = 0.f;
    #pragma unroll
    for (int z = 0; z < KSPLIT; z++)
        s += g_xpart[(size_t)z * MT * DBCW + idx];
    g_dbc[idx] = s;
    int m = idx / DBCW, c = idx - m * DBCW;
    if (c < DR) g_dth[m * DR + permidx(c)] = __float2half_rn(s);
}

// ============================================================================
// Fused causal depthwise conv (k=4) + bias + SiLU.
// g_xs: fp32 (scan). g_xsh: fp16 permuted (x_proj A operand).
// ============================================================================
__global__ __launch_bounds__(256) void conv_silu(
    const float* __restrict__ w, const float* __restrict__ bias)
{
    int idx = blockIdx.x * 256 + threadIdx.x;
    int d = idx & (DI - 1);
    int m = idx >> 11;
    int l = m & (LL - 1);
    float acc = bias[d];
    const float* wd = w + d * 4;
    #pragma unroll
    for (int k = 0; k < 4; k++) {
        int lp = l - 3 + k;
        if (lp >= 0)
            acc = fmaf(g_xz[(size_t)(m - 3 + k) * (2 * DI) + d], wd[k], acc);
    }
    float sig = 1.f / (1.f + __expf(-acc));
    float v = acc * sig;
    g_xs[idx] = v;
    g_xsh[(size_t)m * DI + permidx(d)] = __float2half_rn(v);
}

// ============================================================================
// Selective scan. 16 lanes per (b,d) channel, one lane per state n.
// Block-of-4 register prefetch; loop-carried chain = exp -> fma only.
// Epilogue (n==0): g_yh[m, perm(d)] = fp16((y + D*xs) * silu(z))
// ============================================================================
__global__ __launch_bounds__(256) void scan_kernel(
    const float* __restrict__ A_log, const float* __restrict__ Dp)
{
    int tid = blockIdx.x * 256 + threadIdx.x;
    int n  = tid & 15;
    int hw = tid >> 4;
    int b  = hw >> 11;
    int d  = hw & (DI - 1);
    int pdi = permidx(d);

    float Ac = -__expf(A_log[d * DS + n]);
    float Dd = Dp[d];
    float h = 0.f;
    const int mbase = b * LL;
    const float* pd   = g_delta + d;
    const float* px   = g_xs + d;
    const float* dbcB = g_dbc + DR + n;
    const float* dbcC = g_dbc + DR + DS + n;

    float cdv[4], cxv[4], cBv[4], cCv[4];
    float ndv[4], nxv[4], nBv[4], nCv[4];

    #pragma unroll
    for (int j = 0; j < 4; j++) {
        size_t m = mbase + j;
        cdv[j] = pd[m * DI];
        cxv[j] = px[m * DI];
        cBv[j] = dbcB[m * DBCW];
        cCv[j] = dbcC[m * DBCW];
    }

    for (int lb = 0; lb < LL; lb += 4) {
        if (lb + 4 < LL) {
            #pragma unroll
            for (int j = 0; j < 4; j++) {
                size_t m = mbase + lb + 4 + j;
                ndv[j] = pd[m * DI];
                nxv[j] = px[m * DI];
                nBv[j] = dbcB[m * DBCW];
                nCv[j] = dbcC[m * DBCW];
            }
        }
        #pragma unroll
        for (int j = 0; j < 4; j++) {
            int m = mbase + lb + j;
            float dv = cdv[j], xv = cxv[j];
            float dA = __expf(dv * Ac);
            h = fmaf(dA, h, dv * xv * cBv[j]);
            float s = h * cCv[j];
            s += __shfl_xor_sync(0xffffffffu, s, 8);
            s += __shfl_xor_sync(0xffffffffu, s, 4);
            s += __shfl_xor_sync(0xffffffffu, s, 2);
            s += __shfl_xor_sync(0xffffffffu, s, 1);
            if (n == 0) {
                float zv = g_xz[(size_t)m * (2 * DI) + DI + d];
                float y = fmaf(Dd, xv, s);
                float sig = 1.f / (1.f + __expf(-zv));
                g_yh[(size_t)m * DI + pdi] = __float2half_rn(y * zv * sig);
            }
        }
        #pragma unroll
        for (int j = 0; j < 4; j++) {
            cdv[j] = ndv[j]; cxv[j] = nxv[j];
            cBv[j] = nBv[j]; cCv[j] = nCv[j];
        }
    }
}

// ============================================================================
// Launcher
// ============================================================================
extern "C" void kernel_launch(void* const* d_in, const int* in_sizes, int n_in,
                              void* d_out, int out_size)
{
    const float* x          = (const float*)d_in[0];
    const float* in_proj_w  = (const float*)d_in[1];
    const float* conv_w     = (const float*)d_in[2];
    const float* conv_b     = (const float*)d_in[3];
    const float* x_proj_w   = (const float*)d_in[4];
    const float* dt_proj_w  = (const float*)d_in[5];
    const float* dt_proj_b  = (const float*)d_in[6];
    const float* A_log      = (const float*)d_in[7];
    const float* Dvec       = (const float*)d_in[8];
    const float* out_proj_w = (const float*)d_in[9];
    float* out = (float*)d_out;

    float *xz, *xpart, *delta;
    __half *xh, *w1h, *wxh, *wdth, *woh, *xsh, *dth, *yh;
    cudaGetSymbolAddress((void**)&xz,    g_xz);
    cudaGetSymbolAddress((void**)&xpart, g_xpart);
    cudaGetSymbolAddress((void**)&delta, g_delta);   // FIX: was passed as raw symbol
    cudaGetSymbolAddress((void**)&xh,    g_xh);
    cudaGetSymbolAddress((void**)&w1h,   g_w1h);
    cudaGetSymbolAddress((void**)&wxh,   g_wxh);
    cudaGetSymbolAddress((void**)&wdth,  g_wdth);
    cudaGetSymbolAddress((void**)&woh,   g_woh);
    cudaGetSymbolAddress((void**)&xsh,   g_xsh);
    cudaGetSymbolAddress((void**)&dth,   g_dth);
    cudaGetSymbolAddress((void**)&yh,    g_yh);

    // 0) fp16-convert + permute x and all weights
    to_half_perm<<<(NBLKH + 255) / 256, 256>>>(x, in_proj_w, x_proj_w,
                                               dt_proj_w, out_proj_w);

    // 1) in_proj: [2048,1024] x [4096,1024]^T -> [2048,4096]
    gemm_h<4, 0, 0><<<dim3((2 * DI) / 128, MT / 128), 256>>>(
        xh, DM, w1h, DM, xz, 2 * DI, DM, nullptr);

    // 2) causal depthwise conv + SiLU
    conv_silu<<<(MT * DI) / 256, 256>>>(conv_w, conv_b);

    // 3) x_proj split-K: [2048,2048] x [96,2048]^T -> 16 partials [2048,96]
    gemm_h<3, 0, 1><<<dim3(1, MT / 128, KSPLIT), 256>>>(
        xsh, DI, wxh, DI, xpart, DBCW, DI / KSPLIT, nullptr);
    reduce_dbc<<<(MT * DBCW + 255) / 256, 256>>>();

    // 4) dt_proj + softplus: [2048,64] x [2048,64]^T -> [2048,2048]
    gemm_h<4, 1, 0><<<dim3(DI / 128, MT / 128), 256>>>(
        dth, DR, wdth, DR, delta, DI, DR, dt_proj_b);

    // 5) selective scan + gating -> g_yh (fp16, permuted)
    scan_kernel<<<(BB * DI * DS) / 256, 256>>>(A_log, Dvec);

    // 6) out_proj: [2048,2048] x [1024,2048]^T -> [2048,1024]
    gemm_h<4, 0, 0><<<dim3(DM / 128, MT / 128), 256>>>(
        yh, DI, woh, DI, out, DM, DI, nullptr);
}

// round 15
// speedup vs baseline: 1.5608x; 1.0194x over previous
#include <cuda_runtime.h>
#include <cuda_fp16.h>
#include <math.h>
#include <stdint.h>

#define DM 1024      // d_model
#define DI 2048      // d_inner
#define DS 16        // d_state
#define DR 64        // dt_rank
#define BB 2         // batch
#define LL 1024      // seq len
#define MT 2048      // BB*LL (token count)
#define DBCW 96      // dt_rank + 2*d_state
#define KSPLIT 16    // split-K factor for x_proj

// ---- scratch (static device allocations; no runtime alloc) ----
// All fp16 GEMM operands are k32-PERMUTED: within each 32-col block, col c
// sits at p32(c), so a thread's m16n8k16 fragment (8 fp16) is one LDS.128.
__device__ float  g_xz[(size_t)MT * 2 * DI];    // in_proj output [MT, 4096]
__device__ float  g_xs[(size_t)MT * DI];        // conv+silu (full fp32)
__device__ float  g_dbc[(size_t)MT * DBCW];     // x_proj output (normal)
__device__ float  g_delta[(size_t)MT * DI];     // softplus(dt) (normal)
__device__ float  g_xpart[(size_t)KSPLIT * MT * DBCW];  // split-K partials
__device__ __half g_xh[(size_t)MT * DM];        // x (fp16, permuted)
__device__ __half g_w1h[(size_t)2 * DI * DM];   // in_proj_w
__device__ __half g_wxh[(size_t)DBCW * DI];     // x_proj_w
__device__ __half g_wdth[(size_t)DI * DR];      // dt_proj_w
__device__ __half g_woh[(size_t)DM * DI];       // out_proj_w
__device__ __half g_xsh[(size_t)MT * DI];       // conv+silu (fp16, permuted)
__device__ __half g_dth[(size_t)MT * DR];       // delta_r (fp16, permuted)
__device__ __half g_yh[(size_t)MT * DI];        // scan out (fp16, permuted)

__device__ __forceinline__ float softplusf(float x) {
    return (x > 20.f) ? x : log1pf(expf(x));
}
__host__ __device__ __forceinline__ int p32(int c) {
    return ((c >> 1) & 3) * 8 + ((c >> 4) & 1) * 4 + ((c >> 3) & 1) * 2 + (c & 1);
}
__device__ __forceinline__ int permidx(int c) {   // permute within 32-blocks
    return (c & ~31) | p32(c & 31);
}
__device__ __forceinline__ void mma_f16(float c[4],
    uint32_t a0, uint32_t a1, uint32_t a2, uint32_t a3, uint32_t b0, uint32_t b1) {
    asm("mma.sync.aligned.m16n8k16.row.col.f32.f16.f16.f32 "
        "{%0,%1,%2,%3}, {%4,%5,%6,%7}, {%8,%9}, {%0,%1,%2,%3};"
        : "+f"(c[0]), "+f"(c[1]), "+f"(c[2]), "+f"(c[3])
        : "r"(a0), "r"(a1), "r"(a2), "r"(a3), "r"(b0), "r"(b1));
}
__device__ __forceinline__ void cp16h(const __half* smem, const __half* g) {
    unsigned s = (unsigned)__cvta_generic_to_shared(smem);
    asm volatile("cp.async.cg.shared.global [%0], [%1], 16;" :: "r"(s), "l"(g));
}

// ============================================================================
// Prepass: fp16-convert + k32-permute x and all GEMM weights.
// ============================================================================
#define B0 (MT * DM / 32)
#define B1 (2 * DI * DM / 32)
#define B2 (DBCW * DI / 32)
#define B3 (DI * DR / 32)
#define B4 (DM * DI / 32)
#define NBLKH (B0 + B1 + B2 + B3 + B4)

__global__ __launch_bounds__(256) void to_half_perm(
    const float* __restrict__ p0, const float* __restrict__ p1,
    const float* __restrict__ p2, const float* __restrict__ p3,
    const float* __restrict__ p4)
{
    int v = blockIdx.x * 256 + threadIdx.x;
    if (v >= NBLKH) return;
    const float* s; __half* d;
    if (v < B0)               { s = p0; d = g_xh;   }
    else if ((v -= B0) < B1)  { s = p1; d = g_w1h;  }
    else if ((v -= B1) < B2)  { s = p2; d = g_wxh;  }
    else if ((v -= B2) < B3)  { s = p3; d = g_wdth; }
    else { v -= B3;             s = p4; d = g_woh;  }
    size_t off = (size_t)v * 32;
    union { __half h[32]; uint4 u[4]; } out;
    #pragma unroll
    for (int q = 0; q < 8; q++) {
        float4 a = *(const float4*)(s + off + q * 4);
        out.h[p32(q * 4 + 0)] = __float2half_rn(a.x);
        out.h[p32(q * 4 + 1)] = __float2half_rn(a.y);
        out.h[p32(q * 4 + 2)] = __float2half_rn(a.z);
        out.h[p32(q * 4 + 3)] = __float2half_rn(a.w);
    }
    uint4* d4 = (uint4*)(d + off);
    d4[0] = out.u[0]; d4[1] = out.u[1]; d4[2] = out.u[2]; d4[3] = out.u[3];
}

// ============================================================================
// fp16 tensor-core GEMM, k32-permuted operands, fp32 accumulate.
// C[M,N] = A[M,K]*B[N,K]^T. CTA 128 x (NT*32), 256 thr (8 warps 2x4),
// warp 64 x (NT*8), mma.m16n8k16.
// K-chunk = 64 per smem stage (two k32 sub-tiles, each stride-32 layout),
// 3-stage cp.async pipeline, wait_group 1 -> 2 chunks in flight, ONE
// __syncthreads per 64-K chunk.
// EPI 1: C = softplus(C + bias[n]).  SPLIT: blockIdx.z = K-chunk partial.
// ============================================================================
template<int NT, int EPI, int SPLIT>
__global__ __launch_bounds__(256, 2) void gemm_h(
    const __half* __restrict__ A, int lda,
    const __half* __restrict__ B, int ldb,
    float* __restrict__ C, int ldc,
    int K, const float* __restrict__ bias)
{
    constexpr int BN = NT * 32;
    constexpr int A_SUB = 128 * 32;             // halfs per A sub-tile
    constexpr int B_SUB = BN * 32;              // halfs per B sub-tile
    constexpr int STAGE = 2 * A_SUB + 2 * B_SUB;
    extern __shared__ __align__(16) __half dsm[];

    const int t    = threadIdx.x;
    const int wid  = t >> 5;
    const int lane = t & 31;
    const int gid  = lane >> 2;
    const int tig  = lane & 3;
    const int m0   = blockIdx.y * 128;
    const int n0   = blockIdx.x * BN;
    const int wm   = (wid >> 2) * 64;
    const int wn   = (wid & 3) * (NT * 8);

    const __half* Ab = A; const __half* Bb = B; float* Cb = C;
    if (SPLIT) {
        int kz = blockIdx.z;
        Ab += (size_t)kz * K;
        Bb += (size_t)kz * K;
        Cb += (size_t)kz * MT * ldc;
    }

    float acc[4][NT][4];
    #pragma unroll
    for (int mi = 0; mi < 4; mi++)
        #pragma unroll
        for (int ni = 0; ni < NT; ni++)
            #pragma unroll
            for (int j = 0; j < 4; j++) acc[mi][ni][j] = 0.f;

    const int niter = K >> 6;   // 64-wide chunks

    // load one 64-K chunk (two k32 sub-tiles) into stage buf
    auto issue = [&](int buf, int kc) {
        __half* st = dsm + buf * STAGE;
        #pragma unroll
        for (int j = 0; j < 2; j++) {
            __half* Aj = st + j * A_SUB;
            __half* Bj = st + 2 * A_SUB + j * B_SUB;
            int k0 = kc + j * 32;
            #pragma unroll
            for (int i = 0; i < 2; i++) {               // A: 512 granules
                int g = t + 256 * i;
                int r = g >> 2, c8 = (g & 3) * 8;
                cp16h(Aj + r * 32 + c8, Ab + (size_t)(m0 + r) * lda + k0 + c8);
            }
            #pragma unroll
            for (int i = 0; i < (BN * 4 + 255) / 256; i++) {  // B: BN*4 granules
                int g = t + 256 * i;
                if ((BN * 4) % 256 == 0 || g < BN * 4) {
                    int r = g >> 2, c8 = (g & 3) * 8;
                    cp16h(Bj + r * 32 + c8, Bb + (size_t)(n0 + r) * ldb + k0 + c8);
                }
            }
        }
        asm volatile("cp.async.commit_group;");
    };

    // compute one k32 sub-tile
    auto compute = [&](const __half* as, const __half* bs) {
        uint4 bq[NT];
        #pragma unroll
        for (int ni = 0; ni < NT; ni++)
            bq[ni] = *(const uint4*)&bs[(wn + ni * 8 + gid) * 32 + tig * 8];
        #pragma unroll
        for (int mi = 0; mi < 4; mi++) {
            int r = wm + mi * 16 + gid;
            uint4 a0 = *(const uint4*)&as[r * 32 + tig * 8];
            uint4 a1 = *(const uint4*)&as[(r + 8) * 32 + tig * 8];
            #pragma unroll
            for (int ni = 0; ni < NT; ni++) {
                mma_f16(acc[mi][ni], a0.x, a1.x, a0.y, a1.y, bq[ni].x, bq[ni].y);
                mma_f16(acc[mi][ni], a0.z, a1.z, a0.w, a1.w, bq[ni].z, bq[ni].w);
            }
        }
    };

    issue(0, 0);
    if (niter > 1) issue(1, 64);

    for (int it = 0; it < niter; ++it) {
        if (it + 1 < niter)
            asm volatile("cp.async.wait_group 1;");
        else
            asm volatile("cp.async.wait_group 0;");
        __syncthreads();
        if (it + 2 < niter) issue((it + 2) % 3, (it + 2) << 6);
        const __half* st = dsm + (it % 3) * STAGE;
        compute(st, st + 2 * A_SUB);
        compute(st + A_SUB, st + 2 * A_SUB + B_SUB);
    }

    #pragma unroll
    for (int mi = 0; mi < 4; mi++) {
        int r0 = m0 + wm + mi * 16 + gid;
        int r1 = r0 + 8;
        #pragma unroll
        for (int ni = 0; ni < NT; ni++) {
            int col = n0 + wn + ni * 8 + tig * 2;
            float v0 = acc[mi][ni][0], v1 = acc[mi][ni][1];
            float v2 = acc[mi][ni][2], v3 = acc[mi][ni][3];
            if (EPI == 1) {
                float b0 = bias[col], b1 = bias[col + 1];
                v0 = softplusf(v0 + b0); v1 = softplusf(v1 + b1);
                v2 = softplusf(v2 + b0); v3 = softplusf(v3 + b1);
            }
            *(float2*)(Cb + (size_t)r0 * ldc + col) = make_float2(v0, v1);
            *(float2*)(Cb + (size_t)r1 * ldc + col) = make_float2(v2, v3);
        }
    }
}

// ============================================================================
// Split-K reduce for x_proj; delta_r -> g_dth (fp16, permuted)
// ============================================================================
__global__ __launch_bounds__(256) void reduce_dbc()
{
    int idx = blockIdx.x * 256 + threadIdx.x;
    if (idx >= MT * DBCW) return;
    float s = 0.f;
    #pragma unroll
    for (int z = 0; z < KSPLIT; z++)
        s += g_xpart[(size_t)z * MT * DBCW + idx];
    g_dbc[idx] = s;
    int m = idx / DBCW, c = idx - m * DBCW;
    if (c < DR) g_dth[m * DR + permidx(c)] = __float2half_rn(s);
}

// ============================================================================
// Fused causal depthwise conv (k=4) + bias + SiLU.
// ============================================================================
__global__ __launch_bounds__(256) void conv_silu(
    const float* __restrict__ w, const float* __restrict__ bias)
{
    int idx = blockIdx.x * 256 + threadIdx.x;
    int d = idx & (DI - 1);
    int m = idx >> 11;
    int l = m & (LL - 1);
    float acc = bias[d];
    const float* wd = w + d * 4;
    #pragma unroll
    for (int k = 0; k < 4; k++) {
        int lp = l - 3 + k;
        if (lp >= 0)
            acc = fmaf(g_xz[(size_t)(m - 3 + k) * (2 * DI) + d], wd[k], acc);
    }
    float sig = 1.f / (1.f + __expf(-acc));
    float v = acc * sig;
    g_xs[idx] = v;
    g_xsh[(size_t)m * DI + permidx(d)] = __float2half_rn(v);
}

// ============================================================================
// Selective scan. 16 lanes per (b,d) channel, one lane per state n.
// ============================================================================
__global__ __launch_bounds__(256) void scan_kernel(
    const float* __restrict__ A_log, const float* __restrict__ Dp)
{
    int tid = blockIdx.x * 256 + threadIdx.x;
    int n  = tid & 15;
    int hw = tid >> 4;
    int b  = hw >> 11;
    int d  = hw & (DI - 1);
    int pdi = permidx(d);

    float Ac = -__expf(A_log[d * DS + n]);
    float Dd = Dp[d];
    float h = 0.f;
    const int mbase = b * LL;
    const float* pd   = g_delta + d;
    const float* px   = g_xs + d;
    const float* dbcB = g_dbc + DR + n;
    const float* dbcC = g_dbc + DR + DS + n;

    float cdv[4], cxv[4], cBv[4], cCv[4];
    float ndv[4], nxv[4], nBv[4], nCv[4];

    #pragma unroll
    for (int j = 0; j < 4; j++) {
        size_t m = mbase + j;
        cdv[j] = pd[m * DI];
        cxv[j] = px[m * DI];
        cBv[j] = dbcB[m * DBCW];
        cCv[j] = dbcC[m * DBCW];
    }

    for (int lb = 0; lb < LL; lb += 4) {
        if (lb + 4 < LL) {
            #pragma unroll
            for (int j = 0; j < 4; j++) {
                size_t m = mbase + lb + 4 + j;
                ndv[j] = pd[m * DI];
                nxv[j] = px[m * DI];
                nBv[j] = dbcB[m * DBCW];
                nCv[j] = dbcC[m * DBCW];
            }
        }
        #pragma unroll
        for (int j = 0; j < 4; j++) {
            int m = mbase + lb + j;
            float dv = cdv[j], xv = cxv[j];
            float dA = __expf(dv * Ac);
            h = fmaf(dA, h, dv * xv * cBv[j]);
            float s = h * cCv[j];
            s += __shfl_xor_sync(0xffffffffu, s, 8);
            s += __shfl_xor_sync(0xffffffffu, s, 4);
            s += __shfl_xor_sync(0xffffffffu, s, 2);
            s += __shfl_xor_sync(0xffffffffu, s, 1);
            if (n == 0) {
                float zv = g_xz[(size_t)m * (2 * DI) + DI + d];
                float y = fmaf(Dd, xv, s);
                float sig = 1.f / (1.f + __expf(-zv));
                g_yh[(size_t)m * DI + pdi] = __float2half_rn(y * zv * sig);
            }
        }
        #pragma unroll
        for (int j = 0; j < 4; j++) {
            cdv[j] = ndv[j]; cxv[j] = nxv[j];
            cBv[j] = nBv[j]; cCv[j] = nCv[j];
        }
    }
}

// ============================================================================
// Launcher
// ============================================================================
extern "C" void kernel_launch(void* const* d_in, const int* in_sizes, int n_in,
                              void* d_out, int out_size)
{
    const float* x          = (const float*)d_in[0];
    const float* in_proj_w  = (const float*)d_in[1];
    const float* conv_w     = (const float*)d_in[2];
    const float* conv_b     = (const float*)d_in[3];
    const float* x_proj_w   = (const float*)d_in[4];
    const float* dt_proj_w  = (const float*)d_in[5];
    const float* dt_proj_b  = (const float*)d_in[6];
    const float* A_log      = (const float*)d_in[7];
    const float* Dvec       = (const float*)d_in[8];
    const float* out_proj_w = (const float*)d_in[9];
    float* out = (float*)d_out;

    float *xz, *xpart, *delta;
    __half *xh, *w1h, *wxh, *wdth, *woh, *xsh, *dth, *yh;
    cudaGetSymbolAddress((void**)&xz,    g_xz);
    cudaGetSymbolAddress((void**)&xpart, g_xpart);
    cudaGetSymbolAddress((void**)&delta, g_delta);
    cudaGetSymbolAddress((void**)&xh,    g_xh);
    cudaGetSymbolAddress((void**)&w1h,   g_w1h);
    cudaGetSymbolAddress((void**)&wxh,   g_wxh);
    cudaGetSymbolAddress((void**)&wdth,  g_wdth);
    cudaGetSymbolAddress((void**)&woh,   g_woh);
    cudaGetSymbolAddress((void**)&xsh,   g_xsh);
    cudaGetSymbolAddress((void**)&dth,   g_dth);
    cudaGetSymbolAddress((void**)&yh,    g_yh);

    // dynamic smem sizes: 3 stages x (2*A_sub + 2*B_sub) halfs
    const int smem4 = 3 * (2 * 128 * 32 + 2 * 128 * 32) * 2;  // NT=4: 96 KB
    const int smem3 = 3 * (2 * 128 * 32 + 2 *  96 * 32) * 2;  // NT=3: 84 KB
    static bool attr_set = false;
    if (!attr_set) {
        cudaFuncSetAttribute(gemm_h<4, 0, 0>,
            cudaFuncAttributeMaxDynamicSharedMemorySize, smem4);
        cudaFuncSetAttribute(gemm_h<3, 0, 1>,
            cudaFuncAttributeMaxDynamicSharedMemorySize, smem3);
        cudaFuncSetAttribute(gemm_h<4, 1, 0>,
            cudaFuncAttributeMaxDynamicSharedMemorySize, smem4);
        attr_set = true;
    }

    // 0) fp16-convert + permute x and all weights
    to_half_perm<<<(NBLKH + 255) / 256, 256>>>(x, in_proj_w, x_proj_w,
                                               dt_proj_w, out_proj_w);

    // 1) in_proj: [2048,1024] x [4096,1024]^T -> [2048,4096]
    gemm_h<4, 0, 0><<<dim3((2 * DI) / 128, MT / 128), 256, smem4>>>(
        xh, DM, w1h, DM, xz, 2 * DI, DM, nullptr);

    // 2) causal depthwise conv + SiLU
    conv_silu<<<(MT * DI) / 256, 256>>>(conv_w, conv_b);

    // 3) x_proj split-K: [2048,2048] x [96,2048]^T -> 16 partials [2048,96]
    gemm_h<3, 0, 1><<<dim3(1, MT / 128, KSPLIT), 256, smem3>>>(
        xsh, DI, wxh, DI, xpart, DBCW, DI / KSPLIT, nullptr);
    reduce_dbc<<<(MT * DBCW + 255) / 256, 256>>>();

    // 4) dt_proj + softplus: [2048,64] x [2048,64]^T -> [2048,2048]
    gemm_h<4, 1, 0><<<dim3(DI / 128, MT / 128), 256, smem4>>>(
        dth, DR, wdth, DR, delta, DI, DR, dt_proj_b);

    // 5) selective scan + gating -> g_yh (fp16, permuted)
    scan_kernel<<<(BB * DI * DS) / 256, 256>>>(A_log, Dvec);

    // 6) out_proj: [2048,2048] x [1024,2048]^T -> [2048,1024]
    gemm_h<4, 0, 0><<<dim3(DM / 128, MT / 128), 256, smem4>>>(
        yh, DI, woh, DI, out, DM, DI, nullptr);
}

// round 16
// speedup vs baseline: 3.0719x; 1.9682x over previous
#include <cuda_runtime.h>
#include <cuda_fp16.h>
#include <math.h>
#include <stdint.h>

#define DM 1024      // d_model
#define DI 2048      // d_inner
#define DS 16        // d_state
#define DR 64        // dt_rank
#define BB 2         // batch
#define LL 1024      // seq len
#define MT 2048      // BB*LL (token count)
#define DBCW 96      // dt_rank + 2*d_state
#define KSPLIT 16    // split-K factor for x_proj

// ---- scratch (static device allocations; no runtime alloc) ----
// fp16 GEMM operands are k32-PERMUTED (p32). g_delta/g_xsT/g_zT are stored
// TRANSPOSED [d][m] so the scan reads contiguous float4 along m.
__device__ float  g_xz[(size_t)MT * 2 * DI];    // in_proj output [MT, 4096]
__device__ float  g_xs[(size_t)MT * DI];        // conv+silu [m][d] fp32
__device__ float  g_xsT[(size_t)DI * MT];       // conv+silu transposed [d][m]
__device__ float  g_zT[(size_t)DI * MT];        // z transposed [d][m]
__device__ float  g_dbc[(size_t)MT * DBCW];     // x_proj output [m][96]
__device__ float  g_delta[(size_t)DI * MT];     // softplus(dt) TRANSPOSED [d][m]
__device__ float  g_xpart[(size_t)KSPLIT * MT * DBCW];  // split-K partials
__device__ __half g_xh[(size_t)MT * DM];        // x (fp16, permuted)
__device__ __half g_w1h[(size_t)2 * DI * DM];   // in_proj_w
__device__ __half g_wxh[(size_t)DBCW * DI];     // x_proj_w
__device__ __half g_wdth[(size_t)DI * DR];      // dt_proj_w
__device__ __half g_woh[(size_t)DM * DI];       // out_proj_w
__device__ __half g_xsh[(size_t)MT * DI];       // conv+silu (fp16, permuted)
__device__ __half g_dth[(size_t)MT * DR];       // delta_r (fp16, permuted)
__device__ __half g_yh[(size_t)MT * DI];        // scan out (fp16, permuted)

__device__ __forceinline__ float softplusf(float x) {
    return (x > 20.f) ? x : log1pf(expf(x));
}
__host__ __device__ __forceinline__ int p32(int c) {
    return ((c >> 1) & 3) * 8 + ((c >> 4) & 1) * 4 + ((c >> 3) & 1) * 2 + (c & 1);
}
__device__ __forceinline__ int permidx(int c) {
    return (c & ~31) | p32(c & 31);
}
__device__ __forceinline__ void mma_f16(float c[4],
    uint32_t a0, uint32_t a1, uint32_t a2, uint32_t a3, uint32_t b0, uint32_t b1) {
    asm("mma.sync.aligned.m16n8k16.row.col.f32.f16.f16.f32 "
        "{%0,%1,%2,%3}, {%4,%5,%6,%7}, {%8,%9}, {%0,%1,%2,%3};"
        : "+f"(c[0]), "+f"(c[1]), "+f"(c[2]), "+f"(c[3])
        : "r"(a0), "r"(a1), "r"(a2), "r"(a3), "r"(b0), "r"(b1));
}
__device__ __forceinline__ void cp16h(const __half* smem, const __half* g) {
    unsigned s = (unsigned)__cvta_generic_to_shared(smem);
    asm volatile("cp.async.cg.shared.global [%0], [%1], 16;" :: "r"(s), "l"(g));
}

// ============================================================================
// Prepass: fp16-convert + k32-permute. Split into 3 launches so in_proj is
// launch #4 (ncu capture slot).
// ============================================================================
__device__ __forceinline__ void half_perm_block(const float* s, __half* d, int v)
{
    size_t off = (size_t)v * 32;
    union { __half h[32]; uint4 u[4]; } out;
    #pragma unroll
    for (int q = 0; q < 8; q++) {
        float4 a = *(const float4*)(s + off + q * 4);
        out.h[p32(q * 4 + 0)] = __float2half_rn(a.x);
        out.h[p32(q * 4 + 1)] = __float2half_rn(a.y);
        out.h[p32(q * 4 + 2)] = __float2half_rn(a.z);
        out.h[p32(q * 4 + 3)] = __float2half_rn(a.w);
    }
    uint4* d4 = (uint4*)(d + off);
    d4[0] = out.u[0]; d4[1] = out.u[1]; d4[2] = out.u[2]; d4[3] = out.u[3];
}

__global__ __launch_bounds__(256) void to_half_one(
    const float* __restrict__ src, __half* __restrict__ dst, int nblk)
{
    int v = blockIdx.x * 256 + threadIdx.x;
    if (v < nblk) half_perm_block(src, dst, v);
}

#define B2 (DBCW * DI / 32)
#define B3 (DI * DR / 32)
#define B4 (DM * DI / 32)
__global__ __launch_bounds__(256) void to_half_rest(
    const float* __restrict__ p2, const float* __restrict__ p3,
    const float* __restrict__ p4)
{
    int v = blockIdx.x * 256 + threadIdx.x;
    if (v < B2)               half_perm_block(p2, g_wxh, v);
    else if ((v -= B2) < B3)  half_perm_block(p3, g_wdth, v);
    else if ((v -= B3) < B4)  half_perm_block(p4, g_woh, v);
}

// ============================================================================
// fp16 tensor-core GEMM, k32-permuted operands, fp32 accumulate.
// CTA 128 x (NT*32), 256 thr (8 warps 2x4), warp 64 x (NT*8), mma.m16n8k16.
// 64-K chunks, 3-stage cp.async pipeline, one __syncthreads per chunk.
// EPI 1: C = softplus(C + bias[col]).  EPI 2: C = softplus(C + bias[row]).
// SPLIT: blockIdx.z = K-chunk partial.
// ============================================================================
template<int NT, int EPI, int SPLIT>
__global__ __launch_bounds__(256, 2) void gemm_h(
    const __half* __restrict__ A, int lda,
    const __half* __restrict__ B, int ldb,
    float* __restrict__ C, int ldc,
    int K, const float* __restrict__ bias)
{
    constexpr int BN = NT * 32;
    constexpr int A_SUB = 128 * 32;
    constexpr int B_SUB = BN * 32;
    constexpr int STAGE = 2 * A_SUB + 2 * B_SUB;
    extern __shared__ __align__(16) __half dsm[];

    const int t    = threadIdx.x;
    const int wid  = t >> 5;
    const int lane = t & 31;
    const int gid  = lane >> 2;
    const int tig  = lane & 3;
    const int m0   = blockIdx.y * 128;
    const int n0   = blockIdx.x * BN;
    const int wm   = (wid >> 2) * 64;
    const int wn   = (wid & 3) * (NT * 8);

    const __half* Ab = A; const __half* Bb = B; float* Cb = C;
    if (SPLIT) {
        int kz = blockIdx.z;
        Ab += (size_t)kz * K;
        Bb += (size_t)kz * K;
        Cb += (size_t)kz * MT * ldc;
    }

    float acc[4][NT][4];
    #pragma unroll
    for (int mi = 0; mi < 4; mi++)
        #pragma unroll
        for (int ni = 0; ni < NT; ni++)
            #pragma unroll
            for (int j = 0; j < 4; j++) acc[mi][ni][j] = 0.f;

    const int niter = K >> 6;

    auto issue = [&](int buf, int kc) {
        __half* st = dsm + buf * STAGE;
        #pragma unroll
        for (int j = 0; j < 2; j++) {
            __half* Aj = st + j * A_SUB;
            __half* Bj = st + 2 * A_SUB + j * B_SUB;
            int k0 = kc + j * 32;
            #pragma unroll
            for (int i = 0; i < 2; i++) {
                int g = t + 256 * i;
                int r = g >> 2, c8 = (g & 3) * 8;
                cp16h(Aj + r * 32 + c8, Ab + (size_t)(m0 + r) * lda + k0 + c8);
            }
            #pragma unroll
            for (int i = 0; i < (BN * 4 + 255) / 256; i++) {
                int g = t + 256 * i;
                if ((BN * 4) % 256 == 0 || g < BN * 4) {
                    int r = g >> 2, c8 = (g & 3) * 8;
                    cp16h(Bj + r * 32 + c8, Bb + (size_t)(n0 + r) * ldb + k0 + c8);
                }
            }
        }
        asm volatile("cp.async.commit_group;");
    };

    auto compute = [&](const __half* as, const __half* bs) {
        uint4 bq[NT];
        #pragma unroll
        for (int ni = 0; ni < NT; ni++)
            bq[ni] = *(const uint4*)&bs[(wn + ni * 8 + gid) * 32 + tig * 8];
        #pragma unroll
        for (int mi = 0; mi < 4; mi++) {
            int r = wm + mi * 16 + gid;
            uint4 a0 = *(const uint4*)&as[r * 32 + tig * 8];
            uint4 a1 = *(const uint4*)&as[(r + 8) * 32 + tig * 8];
            #pragma unroll
            for (int ni = 0; ni < NT; ni++) {
                mma_f16(acc[mi][ni], a0.x, a1.x, a0.y, a1.y, bq[ni].x, bq[ni].y);
                mma_f16(acc[mi][ni], a0.z, a1.z, a0.w, a1.w, bq[ni].z, bq[ni].w);
            }
        }
    };

    issue(0, 0);
    if (niter > 1) issue(1, 64);

    for (int it = 0; it < niter; ++it) {
        if (it + 1 < niter)
            asm volatile("cp.async.wait_group 1;");
        else
            asm volatile("cp.async.wait_group 0;");
        __syncthreads();
        if (it + 2 < niter) issue((it + 2) % 3, (it + 2) << 6);
        const __half* st = dsm + (it % 3) * STAGE;
        compute(st, st + 2 * A_SUB);
        compute(st + A_SUB, st + 2 * A_SUB + B_SUB);
    }

    #pragma unroll
    for (int mi = 0; mi < 4; mi++) {
        int r0 = m0 + wm + mi * 16 + gid;
        int r1 = r0 + 8;
        #pragma unroll
        for (int ni = 0; ni < NT; ni++) {
            int col = n0 + wn + ni * 8 + tig * 2;
            float v0 = acc[mi][ni][0], v1 = acc[mi][ni][1];
            float v2 = acc[mi][ni][2], v3 = acc[mi][ni][3];
            if (EPI == 1) {
                float b0 = bias[col], b1 = bias[col + 1];
                v0 = softplusf(v0 + b0); v1 = softplusf(v1 + b1);
                v2 = softplusf(v2 + b0); v3 = softplusf(v3 + b1);
            }
            if (EPI == 2) {
                float b0 = bias[r0], b1 = bias[r1];
                v0 = softplusf(v0 + b0); v1 = softplusf(v1 + b0);
                v2 = softplusf(v2 + b1); v3 = softplusf(v3 + b1);
            }
            *(float2*)(Cb + (size_t)r0 * ldc + col) = make_float2(v0, v1);
            *(float2*)(Cb + (size_t)r1 * ldc + col) = make_float2(v2, v3);
        }
    }
}

// ============================================================================
// Split-K reduce for x_proj; delta_r -> g_dth (fp16, permuted)
// ============================================================================
__global__ __launch_bounds__(256) void reduce_dbc()
{
    int idx = blockIdx.x * 256 + threadIdx.x;
    if (idx >= MT * DBCW) return;
    float s = 0.f;
    #pragma unroll
    for (int z = 0; z < KSPLIT; z++)
        s += g_xpart[(size_t)z * MT * DBCW + idx];
    g_dbc[idx] = s;
    int m = idx / DBCW, c = idx - m * DBCW;
    if (c < DR) g_dth[m * DR + permidx(c)] = __float2half_rn(s);
}

// ============================================================================
// Fused causal depthwise conv (k=4) + bias + SiLU. [m][d] outputs.
// ============================================================================
__global__ __launch_bounds__(256) void conv_silu(
    const float* __restrict__ w, const float* __restrict__ bias)
{
    int idx = blockIdx.x * 256 + threadIdx.x;
    int d = idx & (DI - 1);
    int m = idx >> 11;
    int l = m & (LL - 1);
    float acc = bias[d];
    const float* wd = w + d * 4;
    #pragma unroll
    for (int k = 0; k < 4; k++) {
        int lp = l - 3 + k;
        if (lp >= 0)
            acc = fmaf(g_xz[(size_t)(m - 3 + k) * (2 * DI) + d], wd[k], acc);
    }
    float sig = 1.f / (1.f + __expf(-acc));
    float v = acc * sig;
    g_xs[idx] = v;
    g_xsh[(size_t)m * DI + permidx(d)] = __float2half_rn(v);
}

// ============================================================================
// Tiled transpose: g_xs -> g_xsT, g_xz z-half -> g_zT. 32x32 tiles, smem 33.
// ============================================================================
__global__ __launch_bounds__(256) void transpose_xz()
{
    __shared__ float tile[32][33];
    int mt = blockIdx.x * 32;
    int dt0 = blockIdx.y * 32;
    int which = blockIdx.z;
    int t = threadIdx.x;
    int c = t & 31, r8 = t >> 5;
    #pragma unroll
    for (int p = 0; p < 4; p++) {
        int m = mt + r8 + p * 8;
        float v = which ? g_xz[(size_t)m * (2 * DI) + DI + dt0 + c]
                        : g_xs[(size_t)m * DI + dt0 + c];
        tile[r8 + p * 8][c] = v;
    }
    __syncthreads();
    #pragma unroll
    for (int p = 0; p < 4; p++) {
        int d = dt0 + r8 + p * 8;
        float v = tile[c][r8 + p * 8];
        if (which) g_zT[(size_t)d * MT + mt + c] = v;
        else       g_xsT[(size_t)d * MT + mt + c] = v;
    }
}

// ============================================================================
// Selective scan. 16 lanes per (b,d) channel, one lane per state n.
// deltaT/xsT/zT are [d][m]: ONE broadcast float4 per stream per 4 steps.
// B/C stay [m][96] broadcast scalars. Double-buffered block-of-4 prefetch.
// Epilogue (n==0): g_yh[m, perm(d)] = fp16((y + D*xs) * silu(z))
// ============================================================================
__global__ __launch_bounds__(256) void scan_kernel(
    const float* __restrict__ A_log, const float* __restrict__ Dp)
{
    int tid = blockIdx.x * 256 + threadIdx.x;
    int n  = tid & 15;
    int hw = tid >> 4;
    int b  = hw >> 11;
    int d  = hw & (DI - 1);
    int pdi = permidx(d);

    float Ac = -__expf(A_log[d * DS + n]);
    float Dd = Dp[d];
    float h = 0.f;
    const int mbase = b * LL;
    const float* pdT = g_delta + (size_t)d * MT + mbase;
    const float* pxT = g_xsT  + (size_t)d * MT + mbase;
    const float* pzT = g_zT   + (size_t)d * MT + mbase;
    const float* dbcB = g_dbc + DR + n;
    const float* dbcC = g_dbc + DR + DS + n;

    float4 cd4, cx4, cz4, nd4, nx4, nz4;
    float cBv[4], cCv[4], nBv[4], nCv[4];

    cd4 = *(const float4*)(pdT);
    cx4 = *(const float4*)(pxT);
    cz4 = *(const float4*)(pzT);
    #pragma unroll
    for (int j = 0; j < 4; j++) {
        size_t m = mbase + j;
        cBv[j] = dbcB[m * DBCW];
        cCv[j] = dbcC[m * DBCW];
    }

    for (int lb = 0; lb < LL; lb += 4) {
        if (lb + 4 < LL) {
            nd4 = *(const float4*)(pdT + lb + 4);
            nx4 = *(const float4*)(pxT + lb + 4);
            nz4 = *(const float4*)(pzT + lb + 4);
            #pragma unroll
            for (int j = 0; j < 4; j++) {
                size_t m = mbase + lb + 4 + j;
                nBv[j] = dbcB[m * DBCW];
                nCv[j] = dbcC[m * DBCW];
            }
        }
        float dvs[4] = {cd4.x, cd4.y, cd4.z, cd4.w};
        float xvs[4] = {cx4.x, cx4.y, cx4.z, cx4.w};
        float zvs[4] = {cz4.x, cz4.y, cz4.z, cz4.w};
        #pragma unroll
        for (int j = 0; j < 4; j++) {
            int m = mbase + lb + j;
            float dv = dvs[j], xv = xvs[j];
            float dA = __expf(dv * Ac);
            h = fmaf(dA, h, dv * xv * cBv[j]);
            float s = h * cCv[j];
            s += __shfl_xor_sync(0xffffffffu, s, 8);
            s += __shfl_xor_sync(0xffffffffu, s, 4);
            s += __shfl_xor_sync(0xffffffffu, s, 2);
            s += __shfl_xor_sync(0xffffffffu, s, 1);
            if (n == 0) {
                float zv = zvs[j];
                float y = fmaf(Dd, xv, s);
                float sig = 1.f / (1.f + __expf(-zv));
                g_yh[(size_t)m * DI + pdi] = __float2half_rn(y * zv * sig);
            }
        }
        cd4 = nd4; cx4 = nx4; cz4 = nz4;
        #pragma unroll
        for (int j = 0; j < 4; j++) { cBv[j] = nBv[j]; cCv[j] = nCv[j]; }
    }
}

// ============================================================================
// Launcher
// ============================================================================
extern "C" void kernel_launch(void* const* d_in, const int* in_sizes, int n_in,
                              void* d_out, int out_size)
{
    const float* x          = (const float*)d_in[0];
    const float* in_proj_w  = (const float*)d_in[1];
    const float* conv_w     = (const float*)d_in[2];
    const float* conv_b     = (const float*)d_in[3];
    const float* x_proj_w   = (const float*)d_in[4];
    const float* dt_proj_w  = (const float*)d_in[5];
    const float* dt_proj_b  = (const float*)d_in[6];
    const float* A_log      = (const float*)d_in[7];
    const float* Dvec       = (const float*)d_in[8];
    const float* out_proj_w = (const float*)d_in[9];
    float* out = (float*)d_out;

    float *xz, *xpart, *delta;
    __half *xh, *w1h, *wxh, *wdth, *woh, *xsh, *dth, *yh;
    cudaGetSymbolAddress((void**)&xz,    g_xz);
    cudaGetSymbolAddress((void**)&xpart, g_xpart);
    cudaGetSymbolAddress((void**)&delta, g_delta);
    cudaGetSymbolAddress((void**)&xh,    g_xh);
    cudaGetSymbolAddress((void**)&w1h,   g_w1h);
    cudaGetSymbolAddress((void**)&wxh,   g_wxh);
    cudaGetSymbolAddress((void**)&wdth,  g_wdth);
    cudaGetSymbolAddress((void**)&woh,   g_woh);
    cudaGetSymbolAddress((void**)&xsh,   g_xsh);
    cudaGetSymbolAddress((void**)&dth,   g_dth);
    cudaGetSymbolAddress((void**)&yh,    g_yh);

    const int smem4 = 3 * (2 * 128 * 32 + 2 * 128 * 32) * 2;  // NT=4: 96 KB
    const int smem3 = 3 * (2 * 128 * 32 + 2 *  96 * 32) * 2;  // NT=3: 84 KB
    static bool attr_set = false;
    if (!attr_set) {
        cudaFuncSetAttribute(gemm_h<4, 0, 0>,
            cudaFuncAttributeMaxDynamicSharedMemorySize, smem4);
        cudaFuncSetAttribute(gemm_h<3, 0, 1>,
            cudaFuncAttributeMaxDynamicSharedMemorySize, smem3);
        cudaFuncSetAttribute(gemm_h<4, 2, 0>,
            cudaFuncAttributeMaxDynamicSharedMemorySize, smem4);
        attr_set = true;
    }

    // 1-3) prepass split into 3 launches (makes in_proj launch #4 for ncu)
    const int nb0 = MT * DM / 32, nb1 = 2 * DI * DM / 32;
    to_half_one<<<(nb0 + 255) / 256, 256>>>(x, xh, nb0);
    to_half_one<<<(nb1 + 255) / 256, 256>>>(in_proj_w, w1h, nb1);
    to_half_rest<<<(B2 + B3 + B4 + 255) / 256, 256>>>(x_proj_w, dt_proj_w, out_proj_w);

    // 4) in_proj: [2048,1024] x [4096,1024]^T -> [2048,4096]
    gemm_h<4, 0, 0><<<dim3((2 * DI) / 128, MT / 128), 256, smem4>>>(
        xh, DM, w1h, DM, xz, 2 * DI, DM, nullptr);

    // 5) causal depthwise conv + SiLU
    conv_silu<<<(MT * DI) / 256, 256>>>(conv_w, conv_b);

    // 6) transpose xs and z into [d][m] layout
    transpose_xz<<<dim3(MT / 32, DI / 32, 2), 256>>>();

    // 7) x_proj split-K: [2048,2048] x [96,2048]^T -> 16 partials [2048,96]
    gemm_h<3, 0, 1><<<dim3(1, MT / 128, KSPLIT), 256, smem3>>>(
        xsh, DI, wxh, DI, xpart, DBCW, DI / KSPLIT, nullptr);
    reduce_dbc<<<(MT * DBCW + 255) / 256, 256>>>();

    // 8) dt_proj TRANSPOSED: deltaT[d][m] = softplus(Wdt[d,:]·dbc[m,:] + b[d])
    gemm_h<4, 2, 0><<<dim3(MT / 128, DI / 128), 256, smem4>>>(
        wdth, DR, dth, DR, delta, MT, DR, dt_proj_b);

    // 9) selective scan + gating -> g_yh (fp16, permuted)
    scan_kernel<<<(BB * DI * DS) / 256, 256>>>(A_log, Dvec);

    // 10) out_proj: [2048,2048] x [1024,2048]^T -> [2048,1024]
    gemm_h<4, 0, 0><<<dim3(DM / 128, MT / 128), 256, smem4>>>(
        yh, DI, woh, DI, out, DM, DI, nullptr);
}